// round 12
// baseline (speedup 1.0000x reference)
#include <cuda_runtime.h>
#include <cuda_bf16.h>
#include <math.h>
#include <stdint.h>

// Problem constants
#define Bb 4
#define Nn 2048
#define Ff 1024
#define De 128
#define NROWS (Bb*Nn)          // 8192
#define GBLOCK 256             // threads per GEMM CTA (8 warps)
#define SM_GX 74               // softmax grid.x (74*4 = 296 CTAs = 2/SM, 1 wave)

// ---------------------------------------------------------------------------
// Device global scratch (no cudaMalloc allowed)
__device__ __nv_bfloat16 g_feat_hi[(size_t)NROWS * Ff];
__device__ __nv_bfloat16 g_feat_lo[(size_t)NROWS * Ff];
__device__ __nv_bfloat16 g_WT_hi[2][De * Ff];       // W^T [128 x 1024], [0]=Wq,[1]=Wk
__device__ __nv_bfloat16 g_WT_lo[2][De * Ff];
__device__ __nv_bfloat16 g_QK_hi[2][(size_t)NROWS * De];  // [0]=Q,[1]=K
__device__ __nv_bfloat16 g_QK_lo[2][(size_t)NROWS * De];
__device__ float  g_base[(size_t)Bb * Nn * Nn];     // 64 MB
__device__ float  g_c0[NROWS];
__device__ float4 g_cpack[NROWS];                   // c^1..c^4 packed, zero-padded
__device__ float  g_received[4 * NROWS];
__device__ unsigned g_done[4];                      // pass completion counters

// ---------------------------------------------------------------------------
__device__ __forceinline__ uint32_t smem_u32(const void* p) {
    uint32_t a;
    asm("{ .reg .u64 t; cvta.to.shared.u64 t, %1; cvt.u32.u64 %0, t; }" : "=r"(a) : "l"(p));
    return a;
}
__device__ __forceinline__ uint32_t sw128(uint32_t o) { return o ^ ((o >> 3) & 0x70); }
__device__ __forceinline__ float ex2f(float x) {
    float y; asm("ex2.approx.f32 %0, %1;" : "=f"(y) : "f"(x)); return y;
}

#define CP_ASYNC16(dst_u32, src_gptr) \
    asm volatile("cp.async.cg.shared.global [%0], [%1], 16;" :: "r"(dst_u32), "l"(src_gptr))
#define CP_COMMIT()  asm volatile("cp.async.commit_group;" ::: "memory")
#define CP_WAIT1()   asm volatile("cp.async.wait_group 1;" ::: "memory")
#define CP_WAIT0()   asm volatile("cp.async.wait_group 0;" ::: "memory")

#define LDMATRIX_X4(r0, r1, r2, r3, addr) \
    asm volatile("ldmatrix.sync.aligned.m8n8.x4.shared.b16 {%0,%1,%2,%3}, [%4];" \
        : "=r"(r0), "=r"(r1), "=r"(r2), "=r"(r3) : "r"(addr))

#define MMA_BF16(acc, a, b0v, b1v) \
    asm volatile("mma.sync.aligned.m16n8k16.row.col.f32.bf16.bf16.f32 " \
        "{%0,%1,%2,%3}, {%4,%5,%6,%7}, {%8,%9}, {%0,%1,%2,%3};" \
        : "+f"((acc)[0]), "+f"((acc)[1]), "+f"((acc)[2]), "+f"((acc)[3]) \
        : "r"((a)[0]), "r"((a)[1]), "r"((a)[2]), "r"((a)[3]), "r"(b0v), "r"(b1v))

// ---------------------------------------------------------------------------
// cp.async one ROWSx64 bf16 tile (rows of 128B) into SW128-swizzled smem
template<int ROWS>
__device__ __forceinline__ void cpasync_tileR(
    uint32_t dst_base, const __nv_bfloat16* src, int strideElems, int tid)
{
#pragma unroll
    for (int u = tid; u < ROWS * 8; u += GBLOCK) {
        int row = u >> 3, seg = u & 7;
        uint32_t dst = dst_base + sw128((uint32_t)(row * 128 + seg * 16));
        const __nv_bfloat16* g = src + (size_t)row * strideElems + seg * 8;
        CP_ASYNC16(dst, g);
    }
}

// Operand block layout (per 128-row x K=128 operand, hi+lo): 64KB
#define OPC_H(c) ((c) * 32768)
#define OPC_L(c) ((c) * 32768 + 16384)
#define OP_BYTES 65536

__device__ __forceinline__ void issue_op(
    uint32_t dst, const __nv_bfloat16* hi, const __nv_bfloat16* lo,
    int strideElems, int tid)
{
#pragma unroll
    for (int c = 0; c < 2; c++) {
        cpasync_tileR<128>(dst + OPC_H(c), hi + c * 64, strideElems, tid);
        cpasync_tileR<128>(dst + OPC_L(c), lo + c * 64, strideElems, tid);
    }
    CP_COMMIT();
}

// compute full K=128, 3-term bf16 split (compat): 8 warps 2Mx4N, warp 64x32
__device__ __forceinline__ void compute_tile(
    uint32_t a_base, uint32_t b_base, int tid, float acc[4][4][4])
{
    const int lane = tid & 31;
    const int wid = tid >> 5;
    const int wm = wid & 1;
    const int wn = wid >> 1;
    const int q = lane >> 3, r = lane & 7;

    const int a_row = r + ((q & 1) ? 8 : 0);
    const int a_colb = ((q & 2) ? 8 : 0) * 2;
    const int b_row = r + ((q & 2) ? 8 : 0);
    const int b_colb = ((q & 1) ? 8 : 0) * 2;

#pragma unroll
    for (int c = 0; c < 2; c++) {
#pragma unroll
        for (int ks = 0; ks < 4; ks++) {
            const int kb2 = ks * 32;

            uint32_t ah[4][4], al[4][4];
#pragma unroll
            for (int mi = 0; mi < 4; mi++) {
                uint32_t off = sw128((uint32_t)((wm * 64 + mi * 16 + a_row) * 128 + kb2 + a_colb));
                LDMATRIX_X4(ah[mi][0], ah[mi][1], ah[mi][2], ah[mi][3], a_base + OPC_H(c) + off);
                LDMATRIX_X4(al[mi][0], al[mi][1], al[mi][2], al[mi][3], a_base + OPC_L(c) + off);
            }
            uint32_t bh[2][4], bl[2][4];
#pragma unroll
            for (int p = 0; p < 2; p++) {
                uint32_t off = sw128((uint32_t)((wn * 32 + p * 16 + b_row) * 128 + kb2 + b_colb));
                LDMATRIX_X4(bh[p][0], bh[p][1], bh[p][2], bh[p][3], b_base + OPC_H(c) + off);
                LDMATRIX_X4(bl[p][0], bl[p][1], bl[p][2], bl[p][3], b_base + OPC_L(c) + off);
            }
#pragma unroll
            for (int mi = 0; mi < 4; mi++)
#pragma unroll
                for (int ni = 0; ni < 4; ni++) {
                    const int p = ni >> 1, s = (ni & 1) * 2;
                    MMA_BF16(acc[mi][ni], ah[mi], bh[p][s], bh[p][s + 1]);
                    MMA_BF16(acc[mi][ni], ah[mi], bl[p][s], bl[p][s + 1]);
                    MMA_BF16(acc[mi][ni], al[mi], bh[p][s], bh[p][s + 1]);
                }
        }
    }
}

// ---------------------------------------------------------------------------
// Fused convert: blocks [0,1024) = feature split + initial charge;
// blocks [1024,2048) = W transpose/split + zero accumulators.
__global__ __launch_bounds__(256) void convert_all_kernel(
    const float* __restrict__ f, const float* __restrict__ Wq,
    const float* __restrict__ Wk, const float* __restrict__ cw,
    const float* __restrict__ cb)
{
    const int tid = threadIdx.x;
    if (blockIdx.x < 1024) {
        const int row = blockIdx.x * 8 + (tid >> 5);
        const int lane = tid & 31;
        const float4* fr = (const float4*)(f + (size_t)row * Ff);
        const float4* cwv = (const float4*)cw;
        __nv_bfloat162* ph = (__nv_bfloat162*)(g_feat_hi + (size_t)row * Ff);
        __nv_bfloat162* pl = (__nv_bfloat162*)(g_feat_lo + (size_t)row * Ff);

        float dot = 0.0f;
#pragma unroll
        for (int u = 0; u < 8; u++) {
            int i = lane + u * 32;
            float4 v = fr[i];
            float4 w = cwv[i];
            dot = fmaf(v.x, w.x, dot); dot = fmaf(v.y, w.y, dot);
            dot = fmaf(v.z, w.z, dot); dot = fmaf(v.w, w.w, dot);
            __nv_bfloat16 h0 = __float2bfloat16(v.x), h1 = __float2bfloat16(v.y);
            __nv_bfloat16 h2 = __float2bfloat16(v.z), h3 = __float2bfloat16(v.w);
            ph[2 * i]     = __halves2bfloat162(h0, h1);
            ph[2 * i + 1] = __halves2bfloat162(h2, h3);
            pl[2 * i]     = __halves2bfloat162(
                __float2bfloat16(v.x - __bfloat162float(h0)),
                __float2bfloat16(v.y - __bfloat162float(h1)));
            pl[2 * i + 1] = __halves2bfloat162(
                __float2bfloat16(v.z - __bfloat162float(h2)),
                __float2bfloat16(v.w - __bfloat162float(h3)));
        }
#pragma unroll
        for (int o = 16; o > 0; o >>= 1) dot += __shfl_xor_sync(0xFFFFFFFFu, dot, o);
        if (lane == 0) g_c0[row] = 1.0f / (1.0f + __expf(-(dot + cb[0])));
    } else {
        const int gidx = (blockIdx.x - 1024) * 256 + tid;   // [0, 262144)
        const int y = gidx >> 17;                           // 0 or 1
        const int idx = gidx & 131071;
        const float* W = y ? Wk : Wq;
        int e = idx >> 10, fidx = idx & 1023;
        float x = W[(size_t)fidx * De + e];
        __nv_bfloat16 h = __float2bfloat16(x);
        g_WT_hi[y][idx] = h;
        g_WT_lo[y][idx] = __float2bfloat16(x - __bfloat162float(h));
        if (gidx < 4) g_done[gidx] = 0u;
        if (gidx < 4 * NROWS) g_received[gidx] = 0.0f;
        else if (gidx < 8 * NROWS) ((float*)g_cpack)[gidx - 4 * NROWS] = 0.0f;
    }
}

// ---------------------------------------------------------------------------
// Projection GEMM: M-tile 64, grid (128, 2), 256 threads, 2 CTAs/SM.
#define PJ_A_H 0
#define PJ_A_L 8192
#define PJ_B_H 16384
#define PJ_B_L 32768
#define PJ_STAGE 49152
#define PROJ_SMEM (2 * PJ_STAGE)    // 98304

__device__ __forceinline__ void proj_issue_chunk(
    uint32_t sbuf, const __nv_bfloat16* Ah, const __nv_bfloat16* Al,
    const __nv_bfloat16* Bh, const __nv_bfloat16* Bl, int c, int tid)
{
    cpasync_tileR<64>(sbuf + PJ_A_H, Ah + c * 64, Ff, tid);
    cpasync_tileR<64>(sbuf + PJ_A_L, Al + c * 64, Ff, tid);
    cpasync_tileR<128>(sbuf + PJ_B_H, Bh + c * 64, Ff, tid);
    cpasync_tileR<128>(sbuf + PJ_B_L, Bl + c * 64, Ff, tid);
    CP_COMMIT();
}

// 8 warps: 2 in M (32 rows each) x 4 in N (32 cols); warp tile 32x32.
__device__ __forceinline__ void proj_compute_chunk(uint32_t sbuf, int tid, float acc[2][4][4])
{
    const int lane = tid & 31;
    const int wid = tid >> 5;
    const int wm = wid & 1, wn = wid >> 1;
    const int q = lane >> 3, r = lane & 7;
    const int a_row = r + ((q & 1) ? 8 : 0);
    const int a_colb = ((q & 2) ? 8 : 0) * 2;
    const int b_row = r + ((q & 2) ? 8 : 0);
    const int b_colb = ((q & 1) ? 8 : 0) * 2;

#pragma unroll
    for (int ks = 0; ks < 4; ks++) {
        const int kb2 = ks * 32;
        uint32_t ah[2][4], al[2][4];
#pragma unroll
        for (int mi = 0; mi < 2; mi++) {
            uint32_t off = sw128((uint32_t)((wm * 32 + mi * 16 + a_row) * 128 + kb2 + a_colb));
            LDMATRIX_X4(ah[mi][0], ah[mi][1], ah[mi][2], ah[mi][3], sbuf + PJ_A_H + off);
            LDMATRIX_X4(al[mi][0], al[mi][1], al[mi][2], al[mi][3], sbuf + PJ_A_L + off);
        }
        uint32_t bh[2][4], bl[2][4];
#pragma unroll
        for (int p = 0; p < 2; p++) {
            uint32_t off = sw128((uint32_t)((wn * 32 + p * 16 + b_row) * 128 + kb2 + b_colb));
            LDMATRIX_X4(bh[p][0], bh[p][1], bh[p][2], bh[p][3], sbuf + PJ_B_H + off);
            LDMATRIX_X4(bl[p][0], bl[p][1], bl[p][2], bl[p][3], sbuf + PJ_B_L + off);
        }
#pragma unroll
        for (int mi = 0; mi < 2; mi++)
#pragma unroll
            for (int ni = 0; ni < 4; ni++) {
                const int p = ni >> 1, s = (ni & 1) * 2;
                MMA_BF16(acc[mi][ni], ah[mi], bh[p][s], bh[p][s + 1]);
                MMA_BF16(acc[mi][ni], ah[mi], bl[p][s], bl[p][s + 1]);
                MMA_BF16(acc[mi][ni], al[mi], bh[p][s], bh[p][s + 1]);
            }
    }
}

__global__ __launch_bounds__(GBLOCK, 2) void proj_mma_kernel() {
    extern __shared__ __align__(1024) char smem[];
    const int tid = threadIdx.x;
    const int y = blockIdx.y;
    const int mBase = blockIdx.x * 64;
    uint32_t sb = smem_u32(smem);

    const __nv_bfloat16* Ah = g_feat_hi + (size_t)mBase * Ff;
    const __nv_bfloat16* Al = g_feat_lo + (size_t)mBase * Ff;
    const __nv_bfloat16* Bh = g_WT_hi[y];
    const __nv_bfloat16* Bl = g_WT_lo[y];

    float acc[2][4][4];
#pragma unroll
    for (int mi = 0; mi < 2; mi++)
#pragma unroll
        for (int ni = 0; ni < 4; ni++)
#pragma unroll
            for (int k = 0; k < 4; k++) acc[mi][ni][k] = 0.0f;

    const int CHUNKS = 16;
    proj_issue_chunk(sb + 0 * PJ_STAGE, Ah, Al, Bh, Bl, 0, tid);
    proj_issue_chunk(sb + 1 * PJ_STAGE, Ah, Al, Bh, Bl, 1, tid);

#pragma unroll 1
    for (int c = 0; c < CHUNKS; c++) {
        if (c + 1 < CHUNKS) { CP_WAIT1(); } else { CP_WAIT0(); }
        __syncthreads();                          // stage c ready
        proj_compute_chunk(sb + (c & 1) * PJ_STAGE, tid, acc);
        __syncthreads();                          // all warps done with stage c
        if (c + 2 < CHUNKS)
            proj_issue_chunk(sb + (c & 1) * PJ_STAGE, Ah, Al, Bh, Bl, c + 2, tid);
    }

    const int lane = tid & 31, wid = tid >> 5;
    const int wm = wid & 1, wn = wid >> 1;
    const int g = lane >> 2, t2 = (lane & 3) * 2;
    __nv_bfloat16* ph = g_QK_hi[y];
    __nv_bfloat16* pl = g_QK_lo[y];
#pragma unroll
    for (int mi = 0; mi < 2; mi++)
#pragma unroll
        for (int ni = 0; ni < 4; ni++) {
            const int cc = wn * 32 + ni * 8 + t2;
#pragma unroll
            for (int half = 0; half < 2; half++) {
                const int rr = mBase + wm * 32 + mi * 16 + g + half * 8;
                float v0 = acc[mi][ni][half * 2], v1 = acc[mi][ni][half * 2 + 1];
                __nv_bfloat16 h0 = __float2bfloat16(v0), h1 = __float2bfloat16(v1);
                __nv_bfloat16 l0 = __float2bfloat16(v0 - __bfloat162float(h0));
                __nv_bfloat16 l1 = __float2bfloat16(v1 - __bfloat162float(h1));
                *(__nv_bfloat162*)(ph + (size_t)rr * De + cc) = __halves2bfloat162(h0, h1);
                *(__nv_bfloat162*)(pl + (size_t)rr * De + cc) = __halves2bfloat162(l0, l1);
            }
        }
}

// ---------------------------------------------------------------------------
// compat GEMM, persistent-j (unchanged)
#define COMPAT_SMEM (1024 + 3 * OP_BYTES)   // 197632
__global__ __launch_bounds__(GBLOCK, 1) void compat_mma_kernel(const float* __restrict__ ls_p) {
    extern __shared__ __align__(1024) char smem[];
    const int tid = threadIdx.x;
    const int jh = blockIdx.x;           // 0..1
    const int iBase = blockIdx.y * 128;  // 16 i-tiles
    const int b = blockIdx.z;
    uint32_t sb = smem_u32(smem);
    const uint32_t A  = sb + 1024;
    const uint32_t B0 = A + OP_BYTES;
    const uint32_t B1 = B0 + OP_BYTES;

    const __nv_bfloat16* Ah = g_QK_hi[0] + (size_t)(b * Nn + iBase) * De;
    const __nv_bfloat16* Al = g_QK_lo[0] + (size_t)(b * Nn + iBase) * De;
    const __nv_bfloat16* Kh = g_QK_hi[1] + (size_t)(b * Nn + jh * 1024) * De;
    const __nv_bfloat16* Kl = g_QK_lo[1] + (size_t)(b * Nn + jh * 1024) * De;

    issue_op(A,  Ah, Al, De, tid);
    issue_op(B0, Kh,            Kl,            De, tid);
    issue_op(B1, Kh + 128 * De, Kl + 128 * De, De, tid);
    CP_WAIT1();
    __syncthreads();

    const float ls = *ls_p;
    const float rsqrtD = 0.08838834764831845f;
    const int lane = tid & 31, wid = tid >> 5;
    const int wm = wid & 1, wn = wid >> 1;
    const int g = lane >> 2, t2 = (lane & 3) * 2;

#pragma unroll 1
    for (int j = 0; j < 8; j++) {
        const uint32_t Bcur = (j & 1) ? B1 : B0;

        float acc[4][4][4];
#pragma unroll
        for (int mi = 0; mi < 4; mi++)
#pragma unroll
            for (int ni = 0; ni < 4; ni++)
#pragma unroll
                for (int k = 0; k < 4; k++) acc[mi][ni][k] = 0.0f;

        compute_tile(A, Bcur, tid, acc);

        const int jBase = jh * 1024 + j * 128;
#pragma unroll
        for (int mi = 0; mi < 4; mi++)
#pragma unroll
            for (int ni = 0; ni < 4; ni++) {
                const int col = jBase + wn * 32 + ni * 8 + t2;
#pragma unroll
                for (int half = 0; half < 2; half++) {
                    const int row = iBase + wm * 64 + mi * 16 + g + half * 8;
                    float d0 = fmaxf(fabsf((float)(row - col)), 1.0f);
                    float d1 = fmaxf(fabsf((float)(row - col - 1)), 1.0f);
                    float2 v;
                    v.x = acc[mi][ni][half * 2]     * rsqrtD + __fdividef(ls, d0);
                    v.y = acc[mi][ni][half * 2 + 1] * rsqrtD + __fdividef(ls, d1);
                    *(float2*)(g_base + ((size_t)(b * Nn + row)) * Nn + col) = v;
                }
            }

        __syncthreads();
        if (j + 2 < 8) {
            issue_op(Bcur, Kh + (size_t)(j + 2) * 128 * De,
                           Kl + (size_t)(j + 2) * 128 * De, De, tid);
            CP_WAIT1();
            __syncthreads();
        } else if (j + 1 < 8) {
            CP_WAIT0();
            __syncthreads();
        }
    }
}

// ---------------------------------------------------------------------------
// Softmax pass: logits = base * (1 + ss * dot4(c_i, c_j)); g_cpack zero-padded.
// Grid (74, 4) = 296 CTAs = 2/SM, one wave; 4-row groups with register
// prefetch; non-output passes fuse the charge update into the last CTA.
__device__ __forceinline__ void sm_load_group(
    int b, int i0, int j0, float bb[4][8])
{
#pragma unroll
    for (int rr = 0; rr < 4; rr++) {
        const float4* p = (const float4*)(g_base + ((size_t)(b * Nn + i0 + rr)) * Nn + j0);
        float4 v0 = p[0], v1 = p[1];
        bb[rr][0] = v0.x; bb[rr][1] = v0.y; bb[rr][2] = v0.z; bb[rr][3] = v0.w;
        bb[rr][4] = v1.x; bb[rr][5] = v1.y; bb[rr][6] = v1.z; bb[rr][7] = v1.w;
    }
}

template<bool WRITE_OUT>
__global__ __launch_bounds__(256, 2) void softmax_pass_kernel(
    int s, float* __restrict__ out, const float* __restrict__ ss_p,
    const float* __restrict__ decay_p)
{
    __shared__ float s_red[2][4][8];
    __shared__ int s_last;
    const int b = blockIdx.y;
    const int tid = threadIdx.x, lane = tid & 31, wid = tid >> 5;
    const float L2E = 1.4426950408889634f;
    const float ssl = (*ss_p) * L2E;
    const int j0 = tid * 8;

    const int rowStart = (blockIdx.x * Nn) / SM_GX;
    const int rowEnd   = ((blockIdx.x + 1) * Nn) / SM_GX;

    float4 cj[8];
#pragma unroll
    for (int t = 0; t < 8; t++) cj[t] = g_cpack[b * Nn + j0 + t];

    float col[8];
#pragma unroll
    for (int t = 0; t < 8; t++) col[t] = 0.0f;

    int par = 0;
    int i0 = rowStart;

    float bb[4][8];
    if (i0 + 4 <= rowEnd) sm_load_group(b, i0, j0, bb);

#pragma unroll 1
    for (; i0 + 4 <= rowEnd; i0 += 4, par ^= 1) {
        const bool nxt = (i0 + 8 <= rowEnd);
        float nbb[4][8];
        if (nxt) sm_load_group(b, i0 + 4, j0, nbb);

        float lsum[4];
#pragma unroll
        for (int rr = 0; rr < 4; rr++) {
            float4 ci = g_cpack[b * Nn + i0 + rr];
            float cx = ci.x * ssl, cy = ci.y * ssl, cz = ci.z * ssl, cw = ci.w * ssl;
            float acc = 0.0f;
#pragma unroll
            for (int t = 0; t < 8; t++) {
                float m = L2E;
                m = fmaf(cx, cj[t].x, m);
                m = fmaf(cy, cj[t].y, m);
                m = fmaf(cz, cj[t].z, m);
                m = fmaf(cw, cj[t].w, m);
                float e = ex2f(bb[rr][t] * m);
                bb[rr][t] = e;
                acc += e;
            }
            lsum[rr] = acc;
        }
#pragma unroll
        for (int o = 16; o > 0; o >>= 1) {
#pragma unroll
            for (int rr = 0; rr < 4; rr++)
                lsum[rr] += __shfl_xor_sync(0xFFFFFFFFu, lsum[rr], o);
        }
        if (lane == 0) {
#pragma unroll
            for (int rr = 0; rr < 4; rr++) s_red[par][rr][wid] = lsum[rr];
        }
        __syncthreads();

#pragma unroll
        for (int rr = 0; rr < 4; rr++) {
            float tot = s_red[par][rr][0];
#pragma unroll
            for (int w = 1; w < 8; w++) tot += s_red[par][rr][w];
            float inv = __fdividef(1.0f, tot);
            if (WRITE_OUT) {
                float4* orow = (float4*)(out + ((size_t)(b * Nn + i0 + rr)) * Nn + j0);
                orow[0] = make_float4(bb[rr][0] * inv, bb[rr][1] * inv, bb[rr][2] * inv, bb[rr][3] * inv);
                orow[1] = make_float4(bb[rr][4] * inv, bb[rr][5] * inv, bb[rr][6] * inv, bb[rr][7] * inv);
            } else {
#pragma unroll
                for (int t = 0; t < 8; t++) col[t] = fmaf(bb[rr][t], inv, col[t]);
            }
        }

        if (nxt) {
#pragma unroll
            for (int rr = 0; rr < 4; rr++)
#pragma unroll
                for (int t = 0; t < 8; t++) bb[rr][t] = nbb[rr][t];
        }
    }

    // tail rows (0..3), one at a time
#pragma unroll 1
    for (; i0 < rowEnd; i0++, par ^= 1) {
        const float4* p = (const float4*)(g_base + ((size_t)(b * Nn + i0)) * Nn + j0);
        float4 v0 = p[0], v1 = p[1];
        float tb[8] = {v0.x, v0.y, v0.z, v0.w, v1.x, v1.y, v1.z, v1.w};

        float4 ci = g_cpack[b * Nn + i0];
        float cx = ci.x * ssl, cy = ci.y * ssl, cz = ci.z * ssl, cw = ci.w * ssl;
        float lsum = 0.0f;
#pragma unroll
        for (int t = 0; t < 8; t++) {
            float m = L2E;
            m = fmaf(cx, cj[t].x, m);
            m = fmaf(cy, cj[t].y, m);
            m = fmaf(cz, cj[t].z, m);
            m = fmaf(cw, cj[t].w, m);
            float e = ex2f(tb[t] * m);
            tb[t] = e;
            lsum += e;
        }
#pragma unroll
        for (int o = 16; o > 0; o >>= 1) lsum += __shfl_xor_sync(0xFFFFFFFFu, lsum, o);
        if (lane == 0) s_red[par][0][wid] = lsum;
        __syncthreads();
        float tot = s_red[par][0][0];
#pragma unroll
        for (int w = 1; w < 8; w++) tot += s_red[par][0][w];
        float inv = __fdividef(1.0f, tot);
        if (WRITE_OUT) {
            float4* orow = (float4*)(out + ((size_t)(b * Nn + i0)) * Nn + j0);
            orow[0] = make_float4(tb[0] * inv, tb[1] * inv, tb[2] * inv, tb[3] * inv);
            orow[1] = make_float4(tb[4] * inv, tb[5] * inv, tb[6] * inv, tb[7] * inv);
        } else {
#pragma unroll
            for (int t = 0; t < 8; t++) col[t] = fmaf(tb[t], inv, col[t]);
        }
    }

    if (!WRITE_OUT) {
        float* recv = g_received + (size_t)s * NROWS + b * Nn + j0;
#pragma unroll
        for (int t = 0; t < 8; t++) atomicAdd(&recv[t], col[t]);

        // fused charge update: last CTA to finish does it for all rows
        __threadfence();
        __syncthreads();
        if (tid == 0)
            s_last = (atomicAdd(&g_done[s], 1u) == (unsigned)(SM_GX * Bb - 1));
        __syncthreads();
        if (s_last) {
            const float decay = *decay_p;
#pragma unroll 1
            for (int r = tid; r < NROWS; r += 256) {
                float rv = __ldcg(&g_received[(size_t)s * NROWS + r]);
                float prev = (s == 0) ? g_c0[r] : ((float*)&g_cpack[r])[s - 1];
                float sig = 1.0f / (1.0f + __expf(-(rv - 1.0f)));
                ((float*)&g_cpack[r])[s] = prev * (1.0f - decay * sig);
            }
        }
    }
}

// ---------------------------------------------------------------------------
extern "C" void kernel_launch(void* const* d_in, const int* in_sizes, int n_in,
                              void* d_out, int out_size)
{
    const float* features = (const float*)d_in[0];
    const float* W_q      = (const float*)d_in[1];
    const float* W_k      = (const float*)d_in[2];
    const float* charge_w = (const float*)d_in[3];
    const float* charge_b = (const float*)d_in[4];
    const float* ls_p     = (const float*)d_in[5];
    const float* ss_p     = (const float*)d_in[6];
    const float* decay_p  = (const float*)d_in[7];
    float* out = (float*)d_out;

    static bool attr_set = false;
    if (!attr_set) {
        cudaFuncSetAttribute(proj_mma_kernel,   cudaFuncAttributeMaxDynamicSharedMemorySize, PROJ_SMEM);
        cudaFuncSetAttribute(compat_mma_kernel, cudaFuncAttributeMaxDynamicSharedMemorySize, COMPAT_SMEM);
        attr_set = true;
    }

    convert_all_kernel<<<2048, 256>>>(features, W_q, W_k, charge_w, charge_b);

    proj_mma_kernel<<<dim3(NROWS / 64, 2), GBLOCK, PROJ_SMEM>>>();
    compat_mma_kernel<<<dim3(2, 16, Bb), GBLOCK, COMPAT_SMEM>>>(ls_p);

    dim3 sgrid(SM_GX, Bb);
    for (int s = 0; s < 4; s++)
        softmax_pass_kernel<false><<<sgrid, 256>>>(s, nullptr, ss_p, decay_p);
    softmax_pass_kernel<true><<<sgrid, 256>>>(0, out, ss_p, decay_p);
}

// round 13
// speedup vs baseline: 1.2107x; 1.2107x over previous
#include <cuda_runtime.h>
#include <cuda_bf16.h>
#include <math.h>
#include <stdint.h>

// Problem constants
#define Bb 4
#define Nn 2048
#define Ff 1024
#define De 128
#define NROWS (Bb*Nn)          // 8192
#define GBLOCK 256             // threads per GEMM CTA (8 warps)
#define SM_GX 74               // softmax grid.x (74*4 = 296 CTAs = 2/SM, 1 wave)

// ---------------------------------------------------------------------------
// Device global scratch (no cudaMalloc allowed)
__device__ __nv_bfloat16 g_feat_hi[(size_t)NROWS * Ff];
__device__ __nv_bfloat16 g_feat_lo[(size_t)NROWS * Ff];
__device__ __nv_bfloat16 g_WT_hi[2][De * Ff];       // W^T [128 x 1024], [0]=Wq,[1]=Wk
__device__ __nv_bfloat16 g_WT_lo[2][De * Ff];
__device__ __nv_bfloat16 g_QK_hi[2][(size_t)NROWS * De];  // [0]=Q,[1]=K
__device__ __nv_bfloat16 g_QK_lo[2][(size_t)NROWS * De];
__device__ float  g_base[(size_t)Bb * Nn * Nn];     // 64 MB
__device__ float  g_c0[NROWS];
__device__ float4 g_cpack[NROWS];                   // c^1..c^4 packed, zero-padded
__device__ float  g_received[4 * NROWS];

// ---------------------------------------------------------------------------
__device__ __forceinline__ uint32_t smem_u32(const void* p) {
    uint32_t a;
    asm("{ .reg .u64 t; cvta.to.shared.u64 t, %1; cvt.u32.u64 %0, t; }" : "=r"(a) : "l"(p));
    return a;
}
__device__ __forceinline__ uint32_t sw128(uint32_t o) { return o ^ ((o >> 3) & 0x70); }
__device__ __forceinline__ float ex2f(float x) {
    float y; asm("ex2.approx.f32 %0, %1;" : "=f"(y) : "f"(x)); return y;
}

#define CP_ASYNC16(dst_u32, src_gptr) \
    asm volatile("cp.async.cg.shared.global [%0], [%1], 16;" :: "r"(dst_u32), "l"(src_gptr))
#define CP_COMMIT()  asm volatile("cp.async.commit_group;" ::: "memory")
#define CP_WAIT2()   asm volatile("cp.async.wait_group 2;" ::: "memory")
#define CP_WAIT1()   asm volatile("cp.async.wait_group 1;" ::: "memory")
#define CP_WAIT0()   asm volatile("cp.async.wait_group 0;" ::: "memory")

#define LDMATRIX_X4(r0, r1, r2, r3, addr) \
    asm volatile("ldmatrix.sync.aligned.m8n8.x4.shared.b16 {%0,%1,%2,%3}, [%4];" \
        : "=r"(r0), "=r"(r1), "=r"(r2), "=r"(r3) : "r"(addr))

#define MMA_BF16(acc, a, b0v, b1v) \
    asm volatile("mma.sync.aligned.m16n8k16.row.col.f32.bf16.bf16.f32 " \
        "{%0,%1,%2,%3}, {%4,%5,%6,%7}, {%8,%9}, {%0,%1,%2,%3};" \
        : "+f"((acc)[0]), "+f"((acc)[1]), "+f"((acc)[2]), "+f"((acc)[3]) \
        : "r"((a)[0]), "r"((a)[1]), "r"((a)[2]), "r"((a)[3]), "r"(b0v), "r"(b1v))

// ---------------------------------------------------------------------------
// cp.async one ROWSx64 bf16 tile (rows of 128B) into SW128-swizzled smem
template<int ROWS>
__device__ __forceinline__ void cpasync_tileR(
    uint32_t dst_base, const __nv_bfloat16* src, int strideElems, int tid)
{
#pragma unroll
    for (int u = tid; u < ROWS * 8; u += GBLOCK) {
        int row = u >> 3, seg = u & 7;
        uint32_t dst = dst_base + sw128((uint32_t)(row * 128 + seg * 16));
        const __nv_bfloat16* g = src + (size_t)row * strideElems + seg * 8;
        CP_ASYNC16(dst, g);
    }
}

// Operand block layout (per 128-row x K=128 operand, hi+lo): 64KB
#define OPC_H(c) ((c) * 32768)
#define OPC_L(c) ((c) * 32768 + 16384)
#define OP_BYTES 65536

__device__ __forceinline__ void issue_op(
    uint32_t dst, const __nv_bfloat16* hi, const __nv_bfloat16* lo,
    int strideElems, int tid)
{
#pragma unroll
    for (int c = 0; c < 2; c++) {
        cpasync_tileR<128>(dst + OPC_H(c), hi + c * 64, strideElems, tid);
        cpasync_tileR<128>(dst + OPC_L(c), lo + c * 64, strideElems, tid);
    }
    CP_COMMIT();
}

// compute full K=128, 3-term bf16 split (compat): 8 warps 2Mx4N, warp 64x32
__device__ __forceinline__ void compute_tile(
    uint32_t a_base, uint32_t b_base, int tid, float acc[4][4][4])
{
    const int lane = tid & 31;
    const int wid = tid >> 5;
    const int wm = wid & 1;
    const int wn = wid >> 1;
    const int q = lane >> 3, r = lane & 7;

    const int a_row = r + ((q & 1) ? 8 : 0);
    const int a_colb = ((q & 2) ? 8 : 0) * 2;
    const int b_row = r + ((q & 2) ? 8 : 0);
    const int b_colb = ((q & 1) ? 8 : 0) * 2;

#pragma unroll
    for (int c = 0; c < 2; c++) {
#pragma unroll
        for (int ks = 0; ks < 4; ks++) {
            const int kb2 = ks * 32;

            uint32_t ah[4][4], al[4][4];
#pragma unroll
            for (int mi = 0; mi < 4; mi++) {
                uint32_t off = sw128((uint32_t)((wm * 64 + mi * 16 + a_row) * 128 + kb2 + a_colb));
                LDMATRIX_X4(ah[mi][0], ah[mi][1], ah[mi][2], ah[mi][3], a_base + OPC_H(c) + off);
                LDMATRIX_X4(al[mi][0], al[mi][1], al[mi][2], al[mi][3], a_base + OPC_L(c) + off);
            }
            uint32_t bh[2][4], bl[2][4];
#pragma unroll
            for (int p = 0; p < 2; p++) {
                uint32_t off = sw128((uint32_t)((wn * 32 + p * 16 + b_row) * 128 + kb2 + b_colb));
                LDMATRIX_X4(bh[p][0], bh[p][1], bh[p][2], bh[p][3], b_base + OPC_H(c) + off);
                LDMATRIX_X4(bl[p][0], bl[p][1], bl[p][2], bl[p][3], b_base + OPC_L(c) + off);
            }
#pragma unroll
            for (int mi = 0; mi < 4; mi++)
#pragma unroll
                for (int ni = 0; ni < 4; ni++) {
                    const int p = ni >> 1, s = (ni & 1) * 2;
                    MMA_BF16(acc[mi][ni], ah[mi], bh[p][s], bh[p][s + 1]);
                    MMA_BF16(acc[mi][ni], ah[mi], bl[p][s], bl[p][s + 1]);
                    MMA_BF16(acc[mi][ni], al[mi], bh[p][s], bh[p][s + 1]);
                }
        }
    }
}

// ---------------------------------------------------------------------------
// Fused convert: blocks [0,1024) = feature split + initial charge;
// blocks [1024,2048) = W transpose/split + zero accumulators.
__global__ __launch_bounds__(256) void convert_all_kernel(
    const float* __restrict__ f, const float* __restrict__ Wq,
    const float* __restrict__ Wk, const float* __restrict__ cw,
    const float* __restrict__ cb)
{
    const int tid = threadIdx.x;
    if (blockIdx.x < 1024) {
        const int row = blockIdx.x * 8 + (tid >> 5);
        const int lane = tid & 31;
        const float4* fr = (const float4*)(f + (size_t)row * Ff);
        const float4* cwv = (const float4*)cw;
        __nv_bfloat162* ph = (__nv_bfloat162*)(g_feat_hi + (size_t)row * Ff);
        __nv_bfloat162* pl = (__nv_bfloat162*)(g_feat_lo + (size_t)row * Ff);

        float dot = 0.0f;
#pragma unroll
        for (int u = 0; u < 8; u++) {
            int i = lane + u * 32;
            float4 v = fr[i];
            float4 w = cwv[i];
            dot = fmaf(v.x, w.x, dot); dot = fmaf(v.y, w.y, dot);
            dot = fmaf(v.z, w.z, dot); dot = fmaf(v.w, w.w, dot);
            __nv_bfloat16 h0 = __float2bfloat16(v.x), h1 = __float2bfloat16(v.y);
            __nv_bfloat16 h2 = __float2bfloat16(v.z), h3 = __float2bfloat16(v.w);
            ph[2 * i]     = __halves2bfloat162(h0, h1);
            ph[2 * i + 1] = __halves2bfloat162(h2, h3);
            pl[2 * i]     = __halves2bfloat162(
                __float2bfloat16(v.x - __bfloat162float(h0)),
                __float2bfloat16(v.y - __bfloat162float(h1)));
            pl[2 * i + 1] = __halves2bfloat162(
                __float2bfloat16(v.z - __bfloat162float(h2)),
                __float2bfloat16(v.w - __bfloat162float(h3)));
        }
#pragma unroll
        for (int o = 16; o > 0; o >>= 1) dot += __shfl_xor_sync(0xFFFFFFFFu, dot, o);
        if (lane == 0) g_c0[row] = 1.0f / (1.0f + __expf(-(dot + cb[0])));
    } else {
        const int gidx = (blockIdx.x - 1024) * 256 + tid;   // [0, 262144)
        const int y = gidx >> 17;                           // 0 or 1
        const int idx = gidx & 131071;
        const float* W = y ? Wk : Wq;
        int e = idx >> 10, fidx = idx & 1023;
        float x = W[(size_t)fidx * De + e];
        __nv_bfloat16 h = __float2bfloat16(x);
        g_WT_hi[y][idx] = h;
        g_WT_lo[y][idx] = __float2bfloat16(x - __bfloat162float(h));
        if (gidx < 4 * NROWS) g_received[gidx] = 0.0f;
        else if (gidx < 8 * NROWS) ((float*)g_cpack)[gidx - 4 * NROWS] = 0.0f;
    }
}

// ---------------------------------------------------------------------------
// Projection GEMM: M-tile 64, grid (128, 2), 256 threads, 2 CTAs/SM.
#define PJ_A_H 0
#define PJ_A_L 8192
#define PJ_B_H 16384
#define PJ_B_L 32768
#define PJ_STAGE 49152
#define PROJ_SMEM (2 * PJ_STAGE)    // 98304

__device__ __forceinline__ void proj_issue_chunk(
    uint32_t sbuf, const __nv_bfloat16* Ah, const __nv_bfloat16* Al,
    const __nv_bfloat16* Bh, const __nv_bfloat16* Bl, int c, int tid)
{
    cpasync_tileR<64>(sbuf + PJ_A_H, Ah + c * 64, Ff, tid);
    cpasync_tileR<64>(sbuf + PJ_A_L, Al + c * 64, Ff, tid);
    cpasync_tileR<128>(sbuf + PJ_B_H, Bh + c * 64, Ff, tid);
    cpasync_tileR<128>(sbuf + PJ_B_L, Bl + c * 64, Ff, tid);
    CP_COMMIT();
}

// 8 warps: 2 in M (32 rows each) x 4 in N (32 cols); warp tile 32x32.
__device__ __forceinline__ void proj_compute_chunk(uint32_t sbuf, int tid, float acc[2][4][4])
{
    const int lane = tid & 31;
    const int wid = tid >> 5;
    const int wm = wid & 1, wn = wid >> 1;
    const int q = lane >> 3, r = lane & 7;
    const int a_row = r + ((q & 1) ? 8 : 0);
    const int a_colb = ((q & 2) ? 8 : 0) * 2;
    const int b_row = r + ((q & 2) ? 8 : 0);
    const int b_colb = ((q & 1) ? 8 : 0) * 2;

#pragma unroll
    for (int ks = 0; ks < 4; ks++) {
        const int kb2 = ks * 32;
        uint32_t ah[2][4], al[2][4];
#pragma unroll
        for (int mi = 0; mi < 2; mi++) {
            uint32_t off = sw128((uint32_t)((wm * 32 + mi * 16 + a_row) * 128 + kb2 + a_colb));
            LDMATRIX_X4(ah[mi][0], ah[mi][1], ah[mi][2], ah[mi][3], sbuf + PJ_A_H + off);
            LDMATRIX_X4(al[mi][0], al[mi][1], al[mi][2], al[mi][3], sbuf + PJ_A_L + off);
        }
        uint32_t bh[2][4], bl[2][4];
#pragma unroll
        for (int p = 0; p < 2; p++) {
            uint32_t off = sw128((uint32_t)((wn * 32 + p * 16 + b_row) * 128 + kb2 + b_colb));
            LDMATRIX_X4(bh[p][0], bh[p][1], bh[p][2], bh[p][3], sbuf + PJ_B_H + off);
            LDMATRIX_X4(bl[p][0], bl[p][1], bl[p][2], bl[p][3], sbuf + PJ_B_L + off);
        }
#pragma unroll
        for (int mi = 0; mi < 2; mi++)
#pragma unroll
            for (int ni = 0; ni < 4; ni++) {
                const int p = ni >> 1, s = (ni & 1) * 2;
                MMA_BF16(acc[mi][ni], ah[mi], bh[p][s], bh[p][s + 1]);
                MMA_BF16(acc[mi][ni], ah[mi], bl[p][s], bl[p][s + 1]);
                MMA_BF16(acc[mi][ni], al[mi], bh[p][s], bh[p][s + 1]);
            }
    }
}

__global__ __launch_bounds__(GBLOCK, 2) void proj_mma_kernel() {
    extern __shared__ __align__(1024) char smem[];
    const int tid = threadIdx.x;
    const int y = blockIdx.y;
    const int mBase = blockIdx.x * 64;
    uint32_t sb = smem_u32(smem);

    const __nv_bfloat16* Ah = g_feat_hi + (size_t)mBase * Ff;
    const __nv_bfloat16* Al = g_feat_lo + (size_t)mBase * Ff;
    const __nv_bfloat16* Bh = g_WT_hi[y];
    const __nv_bfloat16* Bl = g_WT_lo[y];

    float acc[2][4][4];
#pragma unroll
    for (int mi = 0; mi < 2; mi++)
#pragma unroll
        for (int ni = 0; ni < 4; ni++)
#pragma unroll
            for (int k = 0; k < 4; k++) acc[mi][ni][k] = 0.0f;

    const int CHUNKS = 16;
    proj_issue_chunk(sb + 0 * PJ_STAGE, Ah, Al, Bh, Bl, 0, tid);
    proj_issue_chunk(sb + 1 * PJ_STAGE, Ah, Al, Bh, Bl, 1, tid);

#pragma unroll 1
    for (int c = 0; c < CHUNKS; c++) {
        if (c + 1 < CHUNKS) { CP_WAIT1(); } else { CP_WAIT0(); }
        __syncthreads();                          // stage c ready
        proj_compute_chunk(sb + (c & 1) * PJ_STAGE, tid, acc);
        __syncthreads();                          // all warps done with stage c
        if (c + 2 < CHUNKS)
            proj_issue_chunk(sb + (c & 1) * PJ_STAGE, Ah, Al, Bh, Bl, c + 2, tid);
    }

    const int lane = tid & 31, wid = tid >> 5;
    const int wm = wid & 1, wn = wid >> 1;
    const int g = lane >> 2, t2 = (lane & 3) * 2;
    __nv_bfloat16* ph = g_QK_hi[y];
    __nv_bfloat16* pl = g_QK_lo[y];
#pragma unroll
    for (int mi = 0; mi < 2; mi++)
#pragma unroll
        for (int ni = 0; ni < 4; ni++) {
            const int cc = wn * 32 + ni * 8 + t2;
#pragma unroll
            for (int half = 0; half < 2; half++) {
                const int rr = mBase + wm * 32 + mi * 16 + g + half * 8;
                float v0 = acc[mi][ni][half * 2], v1 = acc[mi][ni][half * 2 + 1];
                __nv_bfloat16 h0 = __float2bfloat16(v0), h1 = __float2bfloat16(v1);
                __nv_bfloat16 l0 = __float2bfloat16(v0 - __bfloat162float(h0));
                __nv_bfloat16 l1 = __float2bfloat16(v1 - __bfloat162float(h1));
                *(__nv_bfloat162*)(ph + (size_t)rr * De + cc) = __halves2bfloat162(h0, h1);
                *(__nv_bfloat162*)(pl + (size_t)rr * De + cc) = __halves2bfloat162(l0, l1);
            }
        }
}

// ---------------------------------------------------------------------------
// compat GEMM, persistent-j (unchanged)
#define COMPAT_SMEM (1024 + 3 * OP_BYTES)   // 197632
__global__ __launch_bounds__(GBLOCK, 1) void compat_mma_kernel(const float* __restrict__ ls_p) {
    extern __shared__ __align__(1024) char smem[];
    const int tid = threadIdx.x;
    const int jh = blockIdx.x;           // 0..1
    const int iBase = blockIdx.y * 128;  // 16 i-tiles
    const int b = blockIdx.z;
    uint32_t sb = smem_u32(smem);
    const uint32_t A  = sb + 1024;
    const uint32_t B0 = A + OP_BYTES;
    const uint32_t B1 = B0 + OP_BYTES;

    const __nv_bfloat16* Ah = g_QK_hi[0] + (size_t)(b * Nn + iBase) * De;
    const __nv_bfloat16* Al = g_QK_lo[0] + (size_t)(b * Nn + iBase) * De;
    const __nv_bfloat16* Kh = g_QK_hi[1] + (size_t)(b * Nn + jh * 1024) * De;
    const __nv_bfloat16* Kl = g_QK_lo[1] + (size_t)(b * Nn + jh * 1024) * De;

    issue_op(A,  Ah, Al, De, tid);
    issue_op(B0, Kh,            Kl,            De, tid);
    issue_op(B1, Kh + 128 * De, Kl + 128 * De, De, tid);
    CP_WAIT1();
    __syncthreads();

    const float ls = *ls_p;
    const float rsqrtD = 0.08838834764831845f;
    const int lane = tid & 31, wid = tid >> 5;
    const int wm = wid & 1, wn = wid >> 1;
    const int g = lane >> 2, t2 = (lane & 3) * 2;

#pragma unroll 1
    for (int j = 0; j < 8; j++) {
        const uint32_t Bcur = (j & 1) ? B1 : B0;

        float acc[4][4][4];
#pragma unroll
        for (int mi = 0; mi < 4; mi++)
#pragma unroll
            for (int ni = 0; ni < 4; ni++)
#pragma unroll
                for (int k = 0; k < 4; k++) acc[mi][ni][k] = 0.0f;

        compute_tile(A, Bcur, tid, acc);

        const int jBase = jh * 1024 + j * 128;
#pragma unroll
        for (int mi = 0; mi < 4; mi++)
#pragma unroll
            for (int ni = 0; ni < 4; ni++) {
                const int col = jBase + wn * 32 + ni * 8 + t2;
#pragma unroll
                for (int half = 0; half < 2; half++) {
                    const int row = iBase + wm * 64 + mi * 16 + g + half * 8;
                    float d0 = fmaxf(fabsf((float)(row - col)), 1.0f);
                    float d1 = fmaxf(fabsf((float)(row - col - 1)), 1.0f);
                    float2 v;
                    v.x = acc[mi][ni][half * 2]     * rsqrtD + __fdividef(ls, d0);
                    v.y = acc[mi][ni][half * 2 + 1] * rsqrtD + __fdividef(ls, d1);
                    *(float2*)(g_base + ((size_t)(b * Nn + row)) * Nn + col) = v;
                }
            }

        __syncthreads();
        if (j + 2 < 8) {
            issue_op(Bcur, Kh + (size_t)(j + 2) * 128 * De,
                           Kl + (size_t)(j + 2) * 128 * De, De, tid);
            CP_WAIT1();
            __syncthreads();
        } else if (j + 1 < 8) {
            CP_WAIT0();
            __syncthreads();
        }
    }
}

// ---------------------------------------------------------------------------
// Softmax pass with cp.async 3-stage smem pipeline.
// Grid (74, 4) = 296 CTAs (2/SM, one wave). Each CTA: 27-28 rows.
// 4-row groups staged through smem (32KB/stage x 3); tail rows direct.
#define SMX_STG   32768
#define SMX_SCI   (3 * SMX_STG)             // 98304: 32 x float4 ci
#define SMX_SRED  (SMX_SCI + 512)           // 98816: 2x4x8 floats
#define SMAX_SMEM (SMX_SRED + 256)          // 99072

__device__ __forceinline__ void smx_issue_group(
    char* smem, int stage, int b, int i0, int tid)
{
    uint32_t dst = smem_u32(smem) + stage * SMX_STG + tid * 32;
#pragma unroll
    for (int rr = 0; rr < 4; rr++) {
        const float* src = g_base + ((size_t)(b * Nn + i0 + rr)) * Nn + tid * 8;
        CP_ASYNC16(dst + rr * 8192, src);
        CP_ASYNC16(dst + rr * 8192 + 16, src + 4);
    }
    CP_COMMIT();
}

template<bool WRITE_OUT>
__global__ __launch_bounds__(256, 2) void softmax_pass_kernel(
    int s, float* __restrict__ out, const float* __restrict__ ss_p)
{
    extern __shared__ __align__(16) char smem[];
    float4* s_ci = (float4*)(smem + SMX_SCI);
    float (*s_red)[4][8] = (float (*)[4][8])(smem + SMX_SRED);

    const int b = blockIdx.y;
    const int tid = threadIdx.x, lane = tid & 31, wid = tid >> 5;
    const float L2E = 1.4426950408889634f;
    const float ssl = (*ss_p) * L2E;
    const int j0 = tid * 8;

    const int rowStart = (blockIdx.x * Nn) / SM_GX;
    const int rowEnd   = ((blockIdx.x + 1) * Nn) / SM_GX;
    const int nR = rowEnd - rowStart;
    const int nG = nR >> 2;          // full 4-row groups (6 or 7)
    const int nT = nR & 3;

    // per-row charges into smem (once)
    if (tid < nR) s_ci[tid] = g_cpack[b * Nn + rowStart + tid];

    float4 cj[8];
#pragma unroll
    for (int t = 0; t < 8; t++) cj[t] = g_cpack[b * Nn + j0 + t];

    float col[8];
#pragma unroll
    for (int t = 0; t < 8; t++) col[t] = 0.0f;

    // pipeline prologue: up to 3 stages in flight
    for (int k = 0; k < 3 && k < nG; k++)
        smx_issue_group(smem, k, b, rowStart + 4 * k, tid);

#pragma unroll 1
    for (int g = 0; g < nG; g++) {
        const int rem = nG - 1 - g;
        if (rem >= 2) { CP_WAIT2(); } else if (rem == 1) { CP_WAIT1(); } else { CP_WAIT0(); }
        __syncthreads();                         // stage data + s_ci visible

        const char* stg = smem + (g % 3) * SMX_STG;
        const int i0 = rowStart + g * 4;

        float lv[4][8];
        float lsum[4];
#pragma unroll
        for (int rr = 0; rr < 4; rr++) {
            float4 a0 = *(const float4*)(stg + rr * 8192 + tid * 32);
            float4 a1 = *(const float4*)(stg + rr * 8192 + tid * 32 + 16);
            float bbv[8] = {a0.x, a0.y, a0.z, a0.w, a1.x, a1.y, a1.z, a1.w};
            float4 ci = s_ci[g * 4 + rr];
            float cx = ci.x * ssl, cy = ci.y * ssl, cz = ci.z * ssl, cw = ci.w * ssl;
            float acc = 0.0f;
#pragma unroll
            for (int t = 0; t < 8; t++) {
                float m = L2E;
                m = fmaf(cx, cj[t].x, m);
                m = fmaf(cy, cj[t].y, m);
                m = fmaf(cz, cj[t].z, m);
                m = fmaf(cw, cj[t].w, m);
                float e = ex2f(bbv[t] * m);
                lv[rr][t] = e;
                acc += e;
            }
            lsum[rr] = acc;
        }
#pragma unroll
        for (int o = 16; o > 0; o >>= 1) {
#pragma unroll
            for (int rr = 0; rr < 4; rr++)
                lsum[rr] += __shfl_xor_sync(0xFFFFFFFFu, lsum[rr], o);
        }
        if (lane == 0) {
#pragma unroll
            for (int rr = 0; rr < 4; rr++) s_red[g & 1][rr][wid] = lsum[rr];
        }
        __syncthreads();                         // s_red visible; stage reads done

#pragma unroll
        for (int rr = 0; rr < 4; rr++) {
            float tot = s_red[g & 1][rr][0];
#pragma unroll
            for (int w = 1; w < 8; w++) tot += s_red[g & 1][rr][w];
            float inv = __fdividef(1.0f, tot);
            if (WRITE_OUT) {
                float4* orow = (float4*)(out + ((size_t)(b * Nn + i0 + rr)) * Nn + j0);
                orow[0] = make_float4(lv[rr][0] * inv, lv[rr][1] * inv, lv[rr][2] * inv, lv[rr][3] * inv);
                orow[1] = make_float4(lv[rr][4] * inv, lv[rr][5] * inv, lv[rr][6] * inv, lv[rr][7] * inv);
            } else {
#pragma unroll
                for (int t = 0; t < 8; t++) col[t] = fmaf(lv[rr][t], inv, col[t]);
            }
        }

        if (g + 3 < nG)
            smx_issue_group(smem, g % 3, b, rowStart + 4 * (g + 3), tid);
    }

    // tail rows (0..3), direct global loads
#pragma unroll 1
    for (int k = 0; k < nT; k++) {
        const int i0 = rowStart + nG * 4 + k;
        const float4* p = (const float4*)(g_base + ((size_t)(b * Nn + i0)) * Nn + j0);
        float4 v0 = p[0], v1 = p[1];
        float tb[8] = {v0.x, v0.y, v0.z, v0.w, v1.x, v1.y, v1.z, v1.w};

        float4 ci = s_ci[nG * 4 + k];
        float cx = ci.x * ssl, cy = ci.y * ssl, cz = ci.z * ssl, cw = ci.w * ssl;
        float lsum = 0.0f;
#pragma unroll
        for (int t = 0; t < 8; t++) {
            float m = L2E;
            m = fmaf(cx, cj[t].x, m);
            m = fmaf(cy, cj[t].y, m);
            m = fmaf(cz, cj[t].z, m);
            m = fmaf(cw, cj[t].w, m);
            float e = ex2f(tb[t] * m);
            tb[t] = e;
            lsum += e;
        }
#pragma unroll
        for (int o = 16; o > 0; o >>= 1) lsum += __shfl_xor_sync(0xFFFFFFFFu, lsum, o);
        if (lane == 0) s_red[k & 1][0][wid] = lsum;
        __syncthreads();
        float tot = s_red[k & 1][0][0];
#pragma unroll
        for (int w = 1; w < 8; w++) tot += s_red[k & 1][0][w];
        float inv = __fdividef(1.0f, tot);
        if (WRITE_OUT) {
            float4* orow = (float4*)(out + ((size_t)(b * Nn + i0)) * Nn + j0);
            orow[0] = make_float4(tb[0] * inv, tb[1] * inv, tb[2] * inv, tb[3] * inv);
            orow[1] = make_float4(tb[4] * inv, tb[5] * inv, tb[6] * inv, tb[7] * inv);
        } else {
#pragma unroll
            for (int t = 0; t < 8; t++) col[t] = fmaf(tb[t], inv, col[t]);
        }
        __syncthreads();
    }

    if (!WRITE_OUT) {
        float* recv = g_received + (size_t)s * NROWS + b * Nn + j0;
#pragma unroll
        for (int t = 0; t < 8; t++) atomicAdd(&recv[t], col[t]);
    }
}

// ---------------------------------------------------------------------------
// charge update: c^{s+1} = c^s * (1 - decay * sigmoid(received_s - 1))
__global__ void charge_update_kernel(int s, const float* __restrict__ decay_p) {
    int r = blockIdx.x * blockDim.x + threadIdx.x;
    if (r >= NROWS) return;
    float recv = g_received[(size_t)s * NROWS + r];
    float prev = (s == 0) ? g_c0[r] : ((float*)&g_cpack[r])[s - 1];
    float sig = 1.0f / (1.0f + __expf(-(recv - 1.0f)));
    ((float*)&g_cpack[r])[s] = prev * (1.0f - (*decay_p) * sig);
}

// ---------------------------------------------------------------------------
extern "C" void kernel_launch(void* const* d_in, const int* in_sizes, int n_in,
                              void* d_out, int out_size)
{
    const float* features = (const float*)d_in[0];
    const float* W_q      = (const float*)d_in[1];
    const float* W_k      = (const float*)d_in[2];
    const float* charge_w = (const float*)d_in[3];
    const float* charge_b = (const float*)d_in[4];
    const float* ls_p     = (const float*)d_in[5];
    const float* ss_p     = (const float*)d_in[6];
    const float* decay_p  = (const float*)d_in[7];
    float* out = (float*)d_out;

    static bool attr_set = false;
    if (!attr_set) {
        cudaFuncSetAttribute(proj_mma_kernel,   cudaFuncAttributeMaxDynamicSharedMemorySize, PROJ_SMEM);
        cudaFuncSetAttribute(compat_mma_kernel, cudaFuncAttributeMaxDynamicSharedMemorySize, COMPAT_SMEM);
        cudaFuncSetAttribute(softmax_pass_kernel<false>, cudaFuncAttributeMaxDynamicSharedMemorySize, SMAX_SMEM);
        cudaFuncSetAttribute(softmax_pass_kernel<true>,  cudaFuncAttributeMaxDynamicSharedMemorySize, SMAX_SMEM);
        attr_set = true;
    }

    convert_all_kernel<<<2048, 256>>>(features, W_q, W_k, charge_w, charge_b);

    proj_mma_kernel<<<dim3(NROWS / 64, 2), GBLOCK, PROJ_SMEM>>>();
    compat_mma_kernel<<<dim3(2, 16, Bb), GBLOCK, COMPAT_SMEM>>>(ls_p);

    dim3 sgrid(SM_GX, Bb);
    for (int s = 0; s < 4; s++) {
        softmax_pass_kernel<false><<<sgrid, 256, SMAX_SMEM>>>(s, nullptr, ss_p);
        charge_update_kernel<<<NROWS / 256, 256>>>(s, decay_p);
    }
    softmax_pass_kernel<true><<<sgrid, 256, SMAX_SMEM>>>(0, out, ss_p);
}

// round 14
// speedup vs baseline: 1.2216x; 1.0089x over previous
#include <cuda_runtime.h>
#include <cuda_bf16.h>
#include <math.h>
#include <stdint.h>

// Problem constants
#define Bb 4
#define Nn 2048
#define Ff 1024
#define De 128
#define NROWS (Bb*Nn)          // 8192
#define GBLOCK 256             // threads per GEMM CTA (8 warps)
#define SM_GX 74               // softmax grid.x (74*4 = 296 CTAs = 2/SM, 1 wave)

// ---------------------------------------------------------------------------
// Device global scratch (no cudaMalloc allowed)
__device__ __nv_bfloat16 g_feat_hi[(size_t)NROWS * Ff];
__device__ __nv_bfloat16 g_feat_lo[(size_t)NROWS * Ff];
__device__ __nv_bfloat16 g_WT_hi[2][De * Ff];       // W^T [128 x 1024], [0]=Wq,[1]=Wk
__device__ __nv_bfloat16 g_WT_lo[2][De * Ff];
__device__ __nv_bfloat16 g_QK_hi[2][(size_t)NROWS * De];  // [0]=Q,[1]=K
__device__ __nv_bfloat16 g_QK_lo[2][(size_t)NROWS * De];
__device__ float  g_base[(size_t)Bb * Nn * Nn];     // 64 MB
__device__ float  g_c0[NROWS];
__device__ float4 g_cpack[NROWS];                   // c^1..c^4 packed, zero-padded
__device__ float  g_received[4 * NROWS];

// ---------------------------------------------------------------------------
__device__ __forceinline__ uint32_t smem_u32(const void* p) {
    uint32_t a;
    asm("{ .reg .u64 t; cvta.to.shared.u64 t, %1; cvt.u32.u64 %0, t; }" : "=r"(a) : "l"(p));
    return a;
}
__device__ __forceinline__ uint32_t sw128(uint32_t o) { return o ^ ((o >> 3) & 0x70); }
__device__ __forceinline__ float ex2f(float x) {
    float y; asm("ex2.approx.f32 %0, %1;" : "=f"(y) : "f"(x)); return y;
}

#define CP_ASYNC16(dst_u32, src_gptr) \
    asm volatile("cp.async.cg.shared.global [%0], [%1], 16;" :: "r"(dst_u32), "l"(src_gptr))
#define CP_COMMIT()  asm volatile("cp.async.commit_group;" ::: "memory")
#define CP_WAIT2()   asm volatile("cp.async.wait_group 2;" ::: "memory")
#define CP_WAIT1()   asm volatile("cp.async.wait_group 1;" ::: "memory")
#define CP_WAIT0()   asm volatile("cp.async.wait_group 0;" ::: "memory")

#define LDMATRIX_X4(r0, r1, r2, r3, addr) \
    asm volatile("ldmatrix.sync.aligned.m8n8.x4.shared.b16 {%0,%1,%2,%3}, [%4];" \
        : "=r"(r0), "=r"(r1), "=r"(r2), "=r"(r3) : "r"(addr))

#define MMA_BF16(acc, a, b0v, b1v) \
    asm volatile("mma.sync.aligned.m16n8k16.row.col.f32.bf16.bf16.f32 " \
        "{%0,%1,%2,%3}, {%4,%5,%6,%7}, {%8,%9}, {%0,%1,%2,%3};" \
        : "+f"((acc)[0]), "+f"((acc)[1]), "+f"((acc)[2]), "+f"((acc)[3]) \
        : "r"((a)[0]), "r"((a)[1]), "r"((a)[2]), "r"((a)[3]), "r"(b0v), "r"(b1v))

// ---------------------------------------------------------------------------
// cp.async one ROWSx64 bf16 tile (rows of 128B) into SW128-swizzled smem
template<int ROWS>
__device__ __forceinline__ void cpasync_tileR(
    uint32_t dst_base, const __nv_bfloat16* src, int strideElems, int tid)
{
#pragma unroll
    for (int u = tid; u < ROWS * 8; u += GBLOCK) {
        int row = u >> 3, seg = u & 7;
        uint32_t dst = dst_base + sw128((uint32_t)(row * 128 + seg * 16));
        const __nv_bfloat16* g = src + (size_t)row * strideElems + seg * 8;
        CP_ASYNC16(dst, g);
    }
}

// Operand block layout (per 128-row x K=128 operand, hi+lo): 64KB
#define OPC_H(c) ((c) * 32768)
#define OPC_L(c) ((c) * 32768 + 16384)
#define OP_BYTES 65536

__device__ __forceinline__ void issue_op(
    uint32_t dst, const __nv_bfloat16* hi, const __nv_bfloat16* lo,
    int strideElems, int tid)
{
#pragma unroll
    for (int c = 0; c < 2; c++) {
        cpasync_tileR<128>(dst + OPC_H(c), hi + c * 64, strideElems, tid);
        cpasync_tileR<128>(dst + OPC_L(c), lo + c * 64, strideElems, tid);
    }
    CP_COMMIT();
}

// compute full K=128, 3-term bf16 split (compat): 8 warps 2Mx4N, warp 64x32
__device__ __forceinline__ void compute_tile(
    uint32_t a_base, uint32_t b_base, int tid, float acc[4][4][4])
{
    const int lane = tid & 31;
    const int wid = tid >> 5;
    const int wm = wid & 1;
    const int wn = wid >> 1;
    const int q = lane >> 3, r = lane & 7;

    const int a_row = r + ((q & 1) ? 8 : 0);
    const int a_colb = ((q & 2) ? 8 : 0) * 2;
    const int b_row = r + ((q & 2) ? 8 : 0);
    const int b_colb = ((q & 1) ? 8 : 0) * 2;

#pragma unroll
    for (int c = 0; c < 2; c++) {
#pragma unroll
        for (int ks = 0; ks < 4; ks++) {
            const int kb2 = ks * 32;

            uint32_t ah[4][4], al[4][4];
#pragma unroll
            for (int mi = 0; mi < 4; mi++) {
                uint32_t off = sw128((uint32_t)((wm * 64 + mi * 16 + a_row) * 128 + kb2 + a_colb));
                LDMATRIX_X4(ah[mi][0], ah[mi][1], ah[mi][2], ah[mi][3], a_base + OPC_H(c) + off);
                LDMATRIX_X4(al[mi][0], al[mi][1], al[mi][2], al[mi][3], a_base + OPC_L(c) + off);
            }
            uint32_t bh[2][4], bl[2][4];
#pragma unroll
            for (int p = 0; p < 2; p++) {
                uint32_t off = sw128((uint32_t)((wn * 32 + p * 16 + b_row) * 128 + kb2 + b_colb));
                LDMATRIX_X4(bh[p][0], bh[p][1], bh[p][2], bh[p][3], b_base + OPC_H(c) + off);
                LDMATRIX_X4(bl[p][0], bl[p][1], bl[p][2], bl[p][3], b_base + OPC_L(c) + off);
            }
#pragma unroll
            for (int mi = 0; mi < 4; mi++)
#pragma unroll
                for (int ni = 0; ni < 4; ni++) {
                    const int p = ni >> 1, s = (ni & 1) * 2;
                    MMA_BF16(acc[mi][ni], ah[mi], bh[p][s], bh[p][s + 1]);
                    MMA_BF16(acc[mi][ni], ah[mi], bl[p][s], bl[p][s + 1]);
                    MMA_BF16(acc[mi][ni], al[mi], bh[p][s], bh[p][s + 1]);
                }
        }
    }
}

// ---------------------------------------------------------------------------
// Fused convert: blocks [0,1024) = feature split + initial charge;
// blocks [1024,2048) = W transpose/split + zero accumulators.
__global__ __launch_bounds__(256) void convert_all_kernel(
    const float* __restrict__ f, const float* __restrict__ Wq,
    const float* __restrict__ Wk, const float* __restrict__ cw,
    const float* __restrict__ cb)
{
    const int tid = threadIdx.x;
    if (blockIdx.x < 1024) {
        const int row = blockIdx.x * 8 + (tid >> 5);
        const int lane = tid & 31;
        const float4* fr = (const float4*)(f + (size_t)row * Ff);
        const float4* cwv = (const float4*)cw;
        __nv_bfloat162* ph = (__nv_bfloat162*)(g_feat_hi + (size_t)row * Ff);
        __nv_bfloat162* pl = (__nv_bfloat162*)(g_feat_lo + (size_t)row * Ff);

        float dot = 0.0f;
#pragma unroll
        for (int u = 0; u < 8; u++) {
            int i = lane + u * 32;
            float4 v = fr[i];
            float4 w = cwv[i];
            dot = fmaf(v.x, w.x, dot); dot = fmaf(v.y, w.y, dot);
            dot = fmaf(v.z, w.z, dot); dot = fmaf(v.w, w.w, dot);
            __nv_bfloat16 h0 = __float2bfloat16(v.x), h1 = __float2bfloat16(v.y);
            __nv_bfloat16 h2 = __float2bfloat16(v.z), h3 = __float2bfloat16(v.w);
            ph[2 * i]     = __halves2bfloat162(h0, h1);
            ph[2 * i + 1] = __halves2bfloat162(h2, h3);
            pl[2 * i]     = __halves2bfloat162(
                __float2bfloat16(v.x - __bfloat162float(h0)),
                __float2bfloat16(v.y - __bfloat162float(h1)));
            pl[2 * i + 1] = __halves2bfloat162(
                __float2bfloat16(v.z - __bfloat162float(h2)),
                __float2bfloat16(v.w - __bfloat162float(h3)));
        }
#pragma unroll
        for (int o = 16; o > 0; o >>= 1) dot += __shfl_xor_sync(0xFFFFFFFFu, dot, o);
        if (lane == 0) g_c0[row] = 1.0f / (1.0f + __expf(-(dot + cb[0])));
    } else {
        const int gidx = (blockIdx.x - 1024) * 256 + tid;   // [0, 262144)
        const int y = gidx >> 17;                           // 0 or 1
        const int idx = gidx & 131071;
        const float* W = y ? Wk : Wq;
        int e = idx >> 10, fidx = idx & 1023;
        float x = W[(size_t)fidx * De + e];
        __nv_bfloat16 h = __float2bfloat16(x);
        g_WT_hi[y][idx] = h;
        g_WT_lo[y][idx] = __float2bfloat16(x - __bfloat162float(h));
        if (gidx < 4 * NROWS) g_received[gidx] = 0.0f;
        else if (gidx < 8 * NROWS) ((float*)g_cpack)[gidx - 4 * NROWS] = 0.0f;
    }
}

// ---------------------------------------------------------------------------
// Projection GEMM: M-tile 64, grid (128, 2), 256 threads, 2 CTAs/SM.
#define PJ_A_H 0
#define PJ_A_L 8192
#define PJ_B_H 16384
#define PJ_B_L 32768
#define PJ_STAGE 49152
#define PROJ_SMEM (2 * PJ_STAGE)    // 98304

__device__ __forceinline__ void proj_issue_chunk(
    uint32_t sbuf, const __nv_bfloat16* Ah, const __nv_bfloat16* Al,
    const __nv_bfloat16* Bh, const __nv_bfloat16* Bl, int c, int tid)
{
    cpasync_tileR<64>(sbuf + PJ_A_H, Ah + c * 64, Ff, tid);
    cpasync_tileR<64>(sbuf + PJ_A_L, Al + c * 64, Ff, tid);
    cpasync_tileR<128>(sbuf + PJ_B_H, Bh + c * 64, Ff, tid);
    cpasync_tileR<128>(sbuf + PJ_B_L, Bl + c * 64, Ff, tid);
    CP_COMMIT();
}

// 8 warps: 2 in M (32 rows each) x 4 in N (32 cols); warp tile 32x32.
__device__ __forceinline__ void proj_compute_chunk(uint32_t sbuf, int tid, float acc[2][4][4])
{
    const int lane = tid & 31;
    const int wid = tid >> 5;
    const int wm = wid & 1, wn = wid >> 1;
    const int q = lane >> 3, r = lane & 7;
    const int a_row = r + ((q & 1) ? 8 : 0);
    const int a_colb = ((q & 2) ? 8 : 0) * 2;
    const int b_row = r + ((q & 2) ? 8 : 0);
    const int b_colb = ((q & 1) ? 8 : 0) * 2;

#pragma unroll
    for (int ks = 0; ks < 4; ks++) {
        const int kb2 = ks * 32;
        uint32_t ah[2][4], al[2][4];
#pragma unroll
        for (int mi = 0; mi < 2; mi++) {
            uint32_t off = sw128((uint32_t)((wm * 32 + mi * 16 + a_row) * 128 + kb2 + a_colb));
            LDMATRIX_X4(ah[mi][0], ah[mi][1], ah[mi][2], ah[mi][3], sbuf + PJ_A_H + off);
            LDMATRIX_X4(al[mi][0], al[mi][1], al[mi][2], al[mi][3], sbuf + PJ_A_L + off);
        }
        uint32_t bh[2][4], bl[2][4];
#pragma unroll
        for (int p = 0; p < 2; p++) {
            uint32_t off = sw128((uint32_t)((wn * 32 + p * 16 + b_row) * 128 + kb2 + b_colb));
            LDMATRIX_X4(bh[p][0], bh[p][1], bh[p][2], bh[p][3], sbuf + PJ_B_H + off);
            LDMATRIX_X4(bl[p][0], bl[p][1], bl[p][2], bl[p][3], sbuf + PJ_B_L + off);
        }
#pragma unroll
        for (int mi = 0; mi < 2; mi++)
#pragma unroll
            for (int ni = 0; ni < 4; ni++) {
                const int p = ni >> 1, s = (ni & 1) * 2;
                MMA_BF16(acc[mi][ni], ah[mi], bh[p][s], bh[p][s + 1]);
                MMA_BF16(acc[mi][ni], ah[mi], bl[p][s], bl[p][s + 1]);
                MMA_BF16(acc[mi][ni], al[mi], bh[p][s], bh[p][s + 1]);
            }
    }
}

__global__ __launch_bounds__(GBLOCK, 2) void proj_mma_kernel() {
    extern __shared__ __align__(1024) char smem[];
    const int tid = threadIdx.x;
    const int y = blockIdx.y;
    const int mBase = blockIdx.x * 64;
    uint32_t sb = smem_u32(smem);

    const __nv_bfloat16* Ah = g_feat_hi + (size_t)mBase * Ff;
    const __nv_bfloat16* Al = g_feat_lo + (size_t)mBase * Ff;
    const __nv_bfloat16* Bh = g_WT_hi[y];
    const __nv_bfloat16* Bl = g_WT_lo[y];

    float acc[2][4][4];
#pragma unroll
    for (int mi = 0; mi < 2; mi++)
#pragma unroll
        for (int ni = 0; ni < 4; ni++)
#pragma unroll
            for (int k = 0; k < 4; k++) acc[mi][ni][k] = 0.0f;

    const int CHUNKS = 16;
    proj_issue_chunk(sb + 0 * PJ_STAGE, Ah, Al, Bh, Bl, 0, tid);
    proj_issue_chunk(sb + 1 * PJ_STAGE, Ah, Al, Bh, Bl, 1, tid);

#pragma unroll 1
    for (int c = 0; c < CHUNKS; c++) {
        if (c + 1 < CHUNKS) { CP_WAIT1(); } else { CP_WAIT0(); }
        __syncthreads();                          // stage c ready
        proj_compute_chunk(sb + (c & 1) * PJ_STAGE, tid, acc);
        __syncthreads();                          // all warps done with stage c
        if (c + 2 < CHUNKS)
            proj_issue_chunk(sb + (c & 1) * PJ_STAGE, Ah, Al, Bh, Bl, c + 2, tid);
    }

    const int lane = tid & 31, wid = tid >> 5;
    const int wm = wid & 1, wn = wid >> 1;
    const int g = lane >> 2, t2 = (lane & 3) * 2;
    __nv_bfloat16* ph = g_QK_hi[y];
    __nv_bfloat16* pl = g_QK_lo[y];
#pragma unroll
    for (int mi = 0; mi < 2; mi++)
#pragma unroll
        for (int ni = 0; ni < 4; ni++) {
            const int cc = wn * 32 + ni * 8 + t2;
#pragma unroll
            for (int half = 0; half < 2; half++) {
                const int rr = mBase + wm * 32 + mi * 16 + g + half * 8;
                float v0 = acc[mi][ni][half * 2], v1 = acc[mi][ni][half * 2 + 1];
                __nv_bfloat16 h0 = __float2bfloat16(v0), h1 = __float2bfloat16(v1);
                __nv_bfloat16 l0 = __float2bfloat16(v0 - __bfloat162float(h0));
                __nv_bfloat16 l1 = __float2bfloat16(v1 - __bfloat162float(h1));
                *(__nv_bfloat162*)(ph + (size_t)rr * De + cc) = __halves2bfloat162(h0, h1);
                *(__nv_bfloat162*)(pl + (size_t)rr * De + cc) = __halves2bfloat162(l0, l1);
            }
        }
}

// ---------------------------------------------------------------------------
// compat GEMM, persistent-j (unchanged)
#define COMPAT_SMEM (1024 + 3 * OP_BYTES)   // 197632
__global__ __launch_bounds__(GBLOCK, 1) void compat_mma_kernel(const float* __restrict__ ls_p) {
    extern __shared__ __align__(1024) char smem[];
    const int tid = threadIdx.x;
    const int jh = blockIdx.x;           // 0..1
    const int iBase = blockIdx.y * 128;  // 16 i-tiles
    const int b = blockIdx.z;
    uint32_t sb = smem_u32(smem);
    const uint32_t A  = sb + 1024;
    const uint32_t B0 = A + OP_BYTES;
    const uint32_t B1 = B0 + OP_BYTES;

    const __nv_bfloat16* Ah = g_QK_hi[0] + (size_t)(b * Nn + iBase) * De;
    const __nv_bfloat16* Al = g_QK_lo[0] + (size_t)(b * Nn + iBase) * De;
    const __nv_bfloat16* Kh = g_QK_hi[1] + (size_t)(b * Nn + jh * 1024) * De;
    const __nv_bfloat16* Kl = g_QK_lo[1] + (size_t)(b * Nn + jh * 1024) * De;

    issue_op(A,  Ah, Al, De, tid);
    issue_op(B0, Kh,            Kl,            De, tid);
    issue_op(B1, Kh + 128 * De, Kl + 128 * De, De, tid);
    CP_WAIT1();
    __syncthreads();

    const float ls = *ls_p;
    const float rsqrtD = 0.08838834764831845f;
    const int lane = tid & 31, wid = tid >> 5;
    const int wm = wid & 1, wn = wid >> 1;
    const int g = lane >> 2, t2 = (lane & 3) * 2;

#pragma unroll 1
    for (int j = 0; j < 8; j++) {
        const uint32_t Bcur = (j & 1) ? B1 : B0;

        float acc[4][4][4];
#pragma unroll
        for (int mi = 0; mi < 4; mi++)
#pragma unroll
            for (int ni = 0; ni < 4; ni++)
#pragma unroll
                for (int k = 0; k < 4; k++) acc[mi][ni][k] = 0.0f;

        compute_tile(A, Bcur, tid, acc);

        const int jBase = jh * 1024 + j * 128;
#pragma unroll
        for (int mi = 0; mi < 4; mi++)
#pragma unroll
            for (int ni = 0; ni < 4; ni++) {
                const int col = jBase + wn * 32 + ni * 8 + t2;
#pragma unroll
                for (int half = 0; half < 2; half++) {
                    const int row = iBase + wm * 64 + mi * 16 + g + half * 8;
                    float d0 = fmaxf(fabsf((float)(row - col)), 1.0f);
                    float d1 = fmaxf(fabsf((float)(row - col - 1)), 1.0f);
                    float2 v;
                    v.x = acc[mi][ni][half * 2]     * rsqrtD + __fdividef(ls, d0);
                    v.y = acc[mi][ni][half * 2 + 1] * rsqrtD + __fdividef(ls, d1);
                    *(float2*)(g_base + ((size_t)(b * Nn + row)) * Nn + col) = v;
                }
            }

        __syncthreads();
        if (j + 2 < 8) {
            issue_op(Bcur, Kh + (size_t)(j + 2) * 128 * De,
                           Kl + (size_t)(j + 2) * 128 * De, De, tid);
            CP_WAIT1();
            __syncthreads();
        } else if (j + 1 < 8) {
            CP_WAIT0();
            __syncthreads();
        }
    }
}

// ---------------------------------------------------------------------------
// Softmax pass with cp.async 3-stage smem pipeline, ONE barrier per group.
// Each thread's cp.async covers exactly the bytes it later reads, so stage
// visibility needs only cp.async.wait_group (no block barrier). Stage reuse
// (g+3) is ordered by the s_red barrier of iteration g.
// Grid (74, 4) = 296 CTAs (2/SM, one wave). Each CTA: 27-28 rows.
#define SMX_STG   32768
#define SMX_SCI   (3 * SMX_STG)             // 98304: 32 x float4 ci
#define SMX_SRED  (SMX_SCI + 512)           // 98816: 2x4x8 floats
#define SMAX_SMEM (SMX_SRED + 256)          // 99072

__device__ __forceinline__ void smx_issue_group(
    char* smem, int stage, int b, int i0, int tid)
{
    uint32_t dst = smem_u32(smem) + stage * SMX_STG + tid * 32;
#pragma unroll
    for (int rr = 0; rr < 4; rr++) {
        const float* src = g_base + ((size_t)(b * Nn + i0 + rr)) * Nn + tid * 8;
        CP_ASYNC16(dst + rr * 8192, src);
        CP_ASYNC16(dst + rr * 8192 + 16, src + 4);
    }
    CP_COMMIT();
}

template<bool WRITE_OUT>
__global__ __launch_bounds__(256, 2) void softmax_pass_kernel(
    int s, float* __restrict__ out, const float* __restrict__ ss_p)
{
    extern __shared__ __align__(16) char smem[];
    float4* s_ci = (float4*)(smem + SMX_SCI);
    float (*s_red)[4][8] = (float (*)[4][8])(smem + SMX_SRED);

    const int b = blockIdx.y;
    const int tid = threadIdx.x, lane = tid & 31, wid = tid >> 5;
    const float L2E = 1.4426950408889634f;
    const float ssl = (*ss_p) * L2E;
    const int j0 = tid * 8;

    const int rowStart = (blockIdx.x * Nn) / SM_GX;
    const int rowEnd   = ((blockIdx.x + 1) * Nn) / SM_GX;
    const int nR = rowEnd - rowStart;
    const int nG = nR >> 2;          // full 4-row groups (6 or 7)
    const int nT = nR & 3;

    // per-row charges into smem (once)
    if (tid < nR) s_ci[tid] = g_cpack[b * Nn + rowStart + tid];

    float4 cj[8];
#pragma unroll
    for (int t = 0; t < 8; t++) cj[t] = g_cpack[b * Nn + j0 + t];

    float col[8];
#pragma unroll
    for (int t = 0; t < 8; t++) col[t] = 0.0f;

    // pipeline prologue: up to 3 stages in flight
    for (int k = 0; k < 3 && k < nG; k++)
        smx_issue_group(smem, k, b, rowStart + 4 * k, tid);

    __syncthreads();                 // s_ci visible to all threads

#pragma unroll 1
    for (int g = 0; g < nG; g++) {
        const int rem = nG - 1 - g;
        if (rem >= 2) { CP_WAIT2(); } else if (rem == 1) { CP_WAIT1(); } else { CP_WAIT0(); }
        // no barrier: each thread reads only its own cp.async data

        const char* stg = smem + (g % 3) * SMX_STG;
        const int i0 = rowStart + g * 4;

        float lv[4][8];
        float lsum[4];
#pragma unroll
        for (int rr = 0; rr < 4; rr++) {
            float4 a0 = *(const float4*)(stg + rr * 8192 + tid * 32);
            float4 a1 = *(const float4*)(stg + rr * 8192 + tid * 32 + 16);
            float bbv[8] = {a0.x, a0.y, a0.z, a0.w, a1.x, a1.y, a1.z, a1.w};
            float4 ci = s_ci[g * 4 + rr];
            float cx = ci.x * ssl, cy = ci.y * ssl, cz = ci.z * ssl, cw = ci.w * ssl;
            float acc = 0.0f;
#pragma unroll
            for (int t = 0; t < 8; t++) {
                float m = L2E;
                m = fmaf(cx, cj[t].x, m);
                m = fmaf(cy, cj[t].y, m);
                m = fmaf(cz, cj[t].z, m);
                m = fmaf(cw, cj[t].w, m);
                float e = ex2f(bbv[t] * m);
                lv[rr][t] = e;
                acc += e;
            }
            lsum[rr] = acc;
        }
#pragma unroll
        for (int o = 16; o > 0; o >>= 1) {
#pragma unroll
            for (int rr = 0; rr < 4; rr++)
                lsum[rr] += __shfl_xor_sync(0xFFFFFFFFu, lsum[rr], o);
        }
        if (lane == 0) {
#pragma unroll
            for (int rr = 0; rr < 4; rr++) s_red[g & 1][rr][wid] = lsum[rr];
        }
        __syncthreads();                         // s_red visible; orders stage reuse

#pragma unroll
        for (int rr = 0; rr < 4; rr++) {
            float tot = s_red[g & 1][rr][0];
#pragma unroll
            for (int w = 1; w < 8; w++) tot += s_red[g & 1][rr][w];
            float inv = __fdividef(1.0f, tot);
            if (WRITE_OUT) {
                float4* orow = (float4*)(out + ((size_t)(b * Nn + i0 + rr)) * Nn + j0);
                orow[0] = make_float4(lv[rr][0] * inv, lv[rr][1] * inv, lv[rr][2] * inv, lv[rr][3] * inv);
                orow[1] = make_float4(lv[rr][4] * inv, lv[rr][5] * inv, lv[rr][6] * inv, lv[rr][7] * inv);
            } else {
#pragma unroll
                for (int t = 0; t < 8; t++) col[t] = fmaf(lv[rr][t], inv, col[t]);
            }
        }

        if (g + 3 < nG)
            smx_issue_group(smem, g % 3, b, rowStart + 4 * (g + 3), tid);
    }

    // tail rows (0..3), direct global loads
#pragma unroll 1
    for (int k = 0; k < nT; k++) {
        const int i0 = rowStart + nG * 4 + k;
        const float4* p = (const float4*)(g_base + ((size_t)(b * Nn + i0)) * Nn + j0);
        float4 v0 = p[0], v1 = p[1];
        float tb[8] = {v0.x, v0.y, v0.z, v0.w, v1.x, v1.y, v1.z, v1.w};

        float4 ci = s_ci[nG * 4 + k];
        float cx = ci.x * ssl, cy = ci.y * ssl, cz = ci.z * ssl, cw = ci.w * ssl;
        float lsum = 0.0f;
#pragma unroll
        for (int t = 0; t < 8; t++) {
            float m = L2E;
            m = fmaf(cx, cj[t].x, m);
            m = fmaf(cy, cj[t].y, m);
            m = fmaf(cz, cj[t].z, m);
            m = fmaf(cw, cj[t].w, m);
            float e = ex2f(tb[t] * m);
            tb[t] = e;
            lsum += e;
        }
#pragma unroll
        for (int o = 16; o > 0; o >>= 1) lsum += __shfl_xor_sync(0xFFFFFFFFu, lsum, o);
        if (lane == 0) s_red[k & 1][0][wid] = lsum;
        __syncthreads();
        float tot = s_red[k & 1][0][0];
#pragma unroll
        for (int w = 1; w < 8; w++) tot += s_red[k & 1][0][w];
        float inv = __fdividef(1.0f, tot);
        if (WRITE_OUT) {
            float4* orow = (float4*)(out + ((size_t)(b * Nn + i0)) * Nn + j0);
            orow[0] = make_float4(tb[0] * inv, tb[1] * inv, tb[2] * inv, tb[3] * inv);
            orow[1] = make_float4(tb[4] * inv, tb[5] * inv, tb[6] * inv, tb[7] * inv);
        } else {
#pragma unroll
            for (int t = 0; t < 8; t++) col[t] = fmaf(tb[t], inv, col[t]);
        }
        __syncthreads();
    }

    if (!WRITE_OUT) {
        float* recv = g_received + (size_t)s * NROWS + b * Nn + j0;
#pragma unroll
        for (int t = 0; t < 8; t++) atomicAdd(&recv[t], col[t]);
    }
}

// ---------------------------------------------------------------------------
// charge update: c^{s+1} = c^s * (1 - decay * sigmoid(received_s - 1))
__global__ void charge_update_kernel(int s, const float* __restrict__ decay_p) {
    int r = blockIdx.x * blockDim.x + threadIdx.x;
    if (r >= NROWS) return;
    float recv = g_received[(size_t)s * NROWS + r];
    float prev = (s == 0) ? g_c0[r] : ((float*)&g_cpack[r])[s - 1];
    float sig = 1.0f / (1.0f + __expf(-(recv - 1.0f)));
    ((float*)&g_cpack[r])[s] = prev * (1.0f - (*decay_p) * sig);
}

// ---------------------------------------------------------------------------
extern "C" void kernel_launch(void* const* d_in, const int* in_sizes, int n_in,
                              void* d_out, int out_size)
{
    const float* features = (const float*)d_in[0];
    const float* W_q      = (const float*)d_in[1];
    const float* W_k      = (const float*)d_in[2];
    const float* charge_w = (const float*)d_in[3];
    const float* charge_b = (const float*)d_in[4];
    const float* ls_p     = (const float*)d_in[5];
    const float* ss_p     = (const float*)d_in[6];
    const float* decay_p  = (const float*)d_in[7];
    float* out = (float*)d_out;

    static bool attr_set = false;
    if (!attr_set) {
        cudaFuncSetAttribute(proj_mma_kernel,   cudaFuncAttributeMaxDynamicSharedMemorySize, PROJ_SMEM);
        cudaFuncSetAttribute(compat_mma_kernel, cudaFuncAttributeMaxDynamicSharedMemorySize, COMPAT_SMEM);
        cudaFuncSetAttribute(softmax_pass_kernel<false>, cudaFuncAttributeMaxDynamicSharedMemorySize, SMAX_SMEM);
        cudaFuncSetAttribute(softmax_pass_kernel<true>,  cudaFuncAttributeMaxDynamicSharedMemorySize, SMAX_SMEM);
        attr_set = true;
    }

    convert_all_kernel<<<2048, 256>>>(features, W_q, W_k, charge_w, charge_b);

    proj_mma_kernel<<<dim3(NROWS / 64, 2), GBLOCK, PROJ_SMEM>>>();
    compat_mma_kernel<<<dim3(2, 16, Bb), GBLOCK, COMPAT_SMEM>>>(ls_p);

    dim3 sgrid(SM_GX, Bb);
    for (int s = 0; s < 4; s++) {
        softmax_pass_kernel<false><<<sgrid, 256, SMAX_SMEM>>>(s, nullptr, ss_p);
        charge_update_kernel<<<NROWS / 256, 256>>>(s, decay_p);
    }
    softmax_pass_kernel<true><<<sgrid, 256, SMAX_SMEM>>>(0, out, ss_p);
}

// round 15
// speedup vs baseline: 1.2619x; 1.0330x over previous
#include <cuda_runtime.h>
#include <cuda_bf16.h>
#include <math.h>
#include <stdint.h>

// Problem constants
#define Bb 4
#define Nn 2048
#define Ff 1024
#define De 128
#define NROWS (Bb*Nn)          // 8192
#define GBLOCK 256             // threads per GEMM CTA (8 warps)
#define SM_GX 74               // softmax grid.x (74*4 = 296 CTAs = 2/SM, 1 wave)

// ---------------------------------------------------------------------------
// Device global scratch (no cudaMalloc allowed)
__device__ __nv_bfloat16 g_feat_hi[(size_t)NROWS * Ff];
__device__ __nv_bfloat16 g_feat_lo[(size_t)NROWS * Ff];
__device__ __nv_bfloat16 g_WT_hi[2][De * Ff];       // W^T [128 x 1024], [0]=Wq,[1]=Wk
__device__ __nv_bfloat16 g_WT_lo[2][De * Ff];
__device__ __nv_bfloat16 g_QK_hi[2][(size_t)NROWS * De];  // [0]=Q,[1]=K
__device__ __nv_bfloat16 g_QK_lo[2][(size_t)NROWS * De];
__device__ float  g_base[(size_t)Bb * Nn * Nn];     // 64 MB
__device__ float  g_c0[NROWS];
__device__ float4 g_cpack[NROWS];                   // c^1..c^4 packed, zero-padded
__device__ float  g_received[4 * NROWS];

// ---------------------------------------------------------------------------
__device__ __forceinline__ uint32_t smem_u32(const void* p) {
    uint32_t a;
    asm("{ .reg .u64 t; cvta.to.shared.u64 t, %1; cvt.u32.u64 %0, t; }" : "=r"(a) : "l"(p));
    return a;
}
__device__ __forceinline__ uint32_t sw128(uint32_t o) { return o ^ ((o >> 3) & 0x70); }
__device__ __forceinline__ float ex2f(float x) {
    float y; asm("ex2.approx.f32 %0, %1;" : "=f"(y) : "f"(x)); return y;
}

#define CP_ASYNC16(dst_u32, src_gptr) \
    asm volatile("cp.async.cg.shared.global [%0], [%1], 16;" :: "r"(dst_u32), "l"(src_gptr))
#define CP_COMMIT()  asm volatile("cp.async.commit_group;" ::: "memory")
#define CP_WAIT2()   asm volatile("cp.async.wait_group 2;" ::: "memory")
#define CP_WAIT1()   asm volatile("cp.async.wait_group 1;" ::: "memory")
#define CP_WAIT0()   asm volatile("cp.async.wait_group 0;" ::: "memory")

#define LDMATRIX_X4(r0, r1, r2, r3, addr) \
    asm volatile("ldmatrix.sync.aligned.m8n8.x4.shared.b16 {%0,%1,%2,%3}, [%4];" \
        : "=r"(r0), "=r"(r1), "=r"(r2), "=r"(r3) : "r"(addr))

#define MMA_BF16(acc, a, b0v, b1v) \
    asm volatile("mma.sync.aligned.m16n8k16.row.col.f32.bf16.bf16.f32 " \
        "{%0,%1,%2,%3}, {%4,%5,%6,%7}, {%8,%9}, {%0,%1,%2,%3};" \
        : "+f"((acc)[0]), "+f"((acc)[1]), "+f"((acc)[2]), "+f"((acc)[3]) \
        : "r"((a)[0]), "r"((a)[1]), "r"((a)[2]), "r"((a)[3]), "r"(b0v), "r"(b1v))

// ---------------------------------------------------------------------------
// cp.async one ROWSx64 bf16 tile (rows of 128B) into SW128-swizzled smem
template<int ROWS>
__device__ __forceinline__ void cpasync_tileR(
    uint32_t dst_base, const __nv_bfloat16* src, int strideElems, int tid)
{
#pragma unroll
    for (int u = tid; u < ROWS * 8; u += GBLOCK) {
        int row = u >> 3, seg = u & 7;
        uint32_t dst = dst_base + sw128((uint32_t)(row * 128 + seg * 16));
        const __nv_bfloat16* g = src + (size_t)row * strideElems + seg * 8;
        CP_ASYNC16(dst, g);
    }
}

// Operand block layout (per 128-row x K=128 operand, hi+lo): 64KB
#define OPC_H(c) ((c) * 32768)
#define OPC_L(c) ((c) * 32768 + 16384)
#define OP_BYTES 65536

__device__ __forceinline__ void issue_op(
    uint32_t dst, const __nv_bfloat16* hi, const __nv_bfloat16* lo,
    int strideElems, int tid)
{
#pragma unroll
    for (int c = 0; c < 2; c++) {
        cpasync_tileR<128>(dst + OPC_H(c), hi + c * 64, strideElems, tid);
        cpasync_tileR<128>(dst + OPC_L(c), lo + c * 64, strideElems, tid);
    }
    CP_COMMIT();
}

// compute full K=128, 3-term bf16 split (compat): 8 warps 2Mx4N, warp 64x32
__device__ __forceinline__ void compute_tile(
    uint32_t a_base, uint32_t b_base, int tid, float acc[4][4][4])
{
    const int lane = tid & 31;
    const int wid = tid >> 5;
    const int wm = wid & 1;
    const int wn = wid >> 1;
    const int q = lane >> 3, r = lane & 7;

    const int a_row = r + ((q & 1) ? 8 : 0);
    const int a_colb = ((q & 2) ? 8 : 0) * 2;
    const int b_row = r + ((q & 2) ? 8 : 0);
    const int b_colb = ((q & 1) ? 8 : 0) * 2;

#pragma unroll
    for (int c = 0; c < 2; c++) {
#pragma unroll
        for (int ks = 0; ks < 4; ks++) {
            const int kb2 = ks * 32;

            uint32_t ah[4][4], al[4][4];
#pragma unroll
            for (int mi = 0; mi < 4; mi++) {
                uint32_t off = sw128((uint32_t)((wm * 64 + mi * 16 + a_row) * 128 + kb2 + a_colb));
                LDMATRIX_X4(ah[mi][0], ah[mi][1], ah[mi][2], ah[mi][3], a_base + OPC_H(c) + off);
                LDMATRIX_X4(al[mi][0], al[mi][1], al[mi][2], al[mi][3], a_base + OPC_L(c) + off);
            }
            uint32_t bh[2][4], bl[2][4];
#pragma unroll
            for (int p = 0; p < 2; p++) {
                uint32_t off = sw128((uint32_t)((wn * 32 + p * 16 + b_row) * 128 + kb2 + b_colb));
                LDMATRIX_X4(bh[p][0], bh[p][1], bh[p][2], bh[p][3], b_base + OPC_H(c) + off);
                LDMATRIX_X4(bl[p][0], bl[p][1], bl[p][2], bl[p][3], b_base + OPC_L(c) + off);
            }
#pragma unroll
            for (int mi = 0; mi < 4; mi++)
#pragma unroll
                for (int ni = 0; ni < 4; ni++) {
                    const int p = ni >> 1, s = (ni & 1) * 2;
                    MMA_BF16(acc[mi][ni], ah[mi], bh[p][s], bh[p][s + 1]);
                    MMA_BF16(acc[mi][ni], ah[mi], bl[p][s], bl[p][s + 1]);
                    MMA_BF16(acc[mi][ni], al[mi], bh[p][s], bh[p][s + 1]);
                }
        }
    }
}

// ---------------------------------------------------------------------------
// Fused convert: blocks [0,1024) = feature split + initial charge;
// blocks [1024,2048) = W transpose/split + zero accumulators.
__global__ __launch_bounds__(256) void convert_all_kernel(
    const float* __restrict__ f, const float* __restrict__ Wq,
    const float* __restrict__ Wk, const float* __restrict__ cw,
    const float* __restrict__ cb)
{
    const int tid = threadIdx.x;
    if (blockIdx.x < 1024) {
        const int row = blockIdx.x * 8 + (tid >> 5);
        const int lane = tid & 31;
        const float4* fr = (const float4*)(f + (size_t)row * Ff);
        const float4* cwv = (const float4*)cw;
        __nv_bfloat162* ph = (__nv_bfloat162*)(g_feat_hi + (size_t)row * Ff);
        __nv_bfloat162* pl = (__nv_bfloat162*)(g_feat_lo + (size_t)row * Ff);

        float dot = 0.0f;
#pragma unroll
        for (int u = 0; u < 8; u++) {
            int i = lane + u * 32;
            float4 v = fr[i];
            float4 w = cwv[i];
            dot = fmaf(v.x, w.x, dot); dot = fmaf(v.y, w.y, dot);
            dot = fmaf(v.z, w.z, dot); dot = fmaf(v.w, w.w, dot);
            __nv_bfloat16 h0 = __float2bfloat16(v.x), h1 = __float2bfloat16(v.y);
            __nv_bfloat16 h2 = __float2bfloat16(v.z), h3 = __float2bfloat16(v.w);
            ph[2 * i]     = __halves2bfloat162(h0, h1);
            ph[2 * i + 1] = __halves2bfloat162(h2, h3);
            pl[2 * i]     = __halves2bfloat162(
                __float2bfloat16(v.x - __bfloat162float(h0)),
                __float2bfloat16(v.y - __bfloat162float(h1)));
            pl[2 * i + 1] = __halves2bfloat162(
                __float2bfloat16(v.z - __bfloat162float(h2)),
                __float2bfloat16(v.w - __bfloat162float(h3)));
        }
#pragma unroll
        for (int o = 16; o > 0; o >>= 1) dot += __shfl_xor_sync(0xFFFFFFFFu, dot, o);
        if (lane == 0) g_c0[row] = 1.0f / (1.0f + __expf(-(dot + cb[0])));
    } else {
        const int gidx = (blockIdx.x - 1024) * 256 + tid;   // [0, 262144)
        const int y = gidx >> 17;                           // 0 or 1
        const int idx = gidx & 131071;
        const float* W = y ? Wk : Wq;
        int e = idx >> 10, fidx = idx & 1023;
        float x = W[(size_t)fidx * De + e];
        __nv_bfloat16 h = __float2bfloat16(x);
        g_WT_hi[y][idx] = h;
        g_WT_lo[y][idx] = __float2bfloat16(x - __bfloat162float(h));
        if (gidx < 4 * NROWS) g_received[gidx] = 0.0f;
        else if (gidx < 8 * NROWS) ((float*)g_cpack)[gidx - 4 * NROWS] = 0.0f;
    }
}

// ---------------------------------------------------------------------------
// Projection GEMM: M-tile 64, grid (128, 2), 256 threads, 2 CTAs/SM.
#define PJ_A_H 0
#define PJ_A_L 8192
#define PJ_B_H 16384
#define PJ_B_L 32768
#define PJ_STAGE 49152
#define PROJ_SMEM (2 * PJ_STAGE)    // 98304

__device__ __forceinline__ void proj_issue_chunk(
    uint32_t sbuf, const __nv_bfloat16* Ah, const __nv_bfloat16* Al,
    const __nv_bfloat16* Bh, const __nv_bfloat16* Bl, int c, int tid)
{
    cpasync_tileR<64>(sbuf + PJ_A_H, Ah + c * 64, Ff, tid);
    cpasync_tileR<64>(sbuf + PJ_A_L, Al + c * 64, Ff, tid);
    cpasync_tileR<128>(sbuf + PJ_B_H, Bh + c * 64, Ff, tid);
    cpasync_tileR<128>(sbuf + PJ_B_L, Bl + c * 64, Ff, tid);
    CP_COMMIT();
}

// 8 warps: 2 in M (32 rows each) x 4 in N (32 cols); warp tile 32x32.
__device__ __forceinline__ void proj_compute_chunk(uint32_t sbuf, int tid, float acc[2][4][4])
{
    const int lane = tid & 31;
    const int wid = tid >> 5;
    const int wm = wid & 1, wn = wid >> 1;
    const int q = lane >> 3, r = lane & 7;
    const int a_row = r + ((q & 1) ? 8 : 0);
    const int a_colb = ((q & 2) ? 8 : 0) * 2;
    const int b_row = r + ((q & 2) ? 8 : 0);
    const int b_colb = ((q & 1) ? 8 : 0) * 2;

#pragma unroll
    for (int ks = 0; ks < 4; ks++) {
        const int kb2 = ks * 32;
        uint32_t ah[2][4], al[2][4];
#pragma unroll
        for (int mi = 0; mi < 2; mi++) {
            uint32_t off = sw128((uint32_t)((wm * 32 + mi * 16 + a_row) * 128 + kb2 + a_colb));
            LDMATRIX_X4(ah[mi][0], ah[mi][1], ah[mi][2], ah[mi][3], sbuf + PJ_A_H + off);
            LDMATRIX_X4(al[mi][0], al[mi][1], al[mi][2], al[mi][3], sbuf + PJ_A_L + off);
        }
        uint32_t bh[2][4], bl[2][4];
#pragma unroll
        for (int p = 0; p < 2; p++) {
            uint32_t off = sw128((uint32_t)((wn * 32 + p * 16 + b_row) * 128 + kb2 + b_colb));
            LDMATRIX_X4(bh[p][0], bh[p][1], bh[p][2], bh[p][3], sbuf + PJ_B_H + off);
            LDMATRIX_X4(bl[p][0], bl[p][1], bl[p][2], bl[p][3], sbuf + PJ_B_L + off);
        }
#pragma unroll
        for (int mi = 0; mi < 2; mi++)
#pragma unroll
            for (int ni = 0; ni < 4; ni++) {
                const int p = ni >> 1, s = (ni & 1) * 2;
                MMA_BF16(acc[mi][ni], ah[mi], bh[p][s], bh[p][s + 1]);
                MMA_BF16(acc[mi][ni], ah[mi], bl[p][s], bl[p][s + 1]);
                MMA_BF16(acc[mi][ni], al[mi], bh[p][s], bh[p][s + 1]);
            }
    }
}

__global__ __launch_bounds__(GBLOCK, 2) void proj_mma_kernel() {
    extern __shared__ __align__(1024) char smem[];
    const int tid = threadIdx.x;
    const int y = blockIdx.y;
    const int mBase = blockIdx.x * 64;
    uint32_t sb = smem_u32(smem);

    const __nv_bfloat16* Ah = g_feat_hi + (size_t)mBase * Ff;
    const __nv_bfloat16* Al = g_feat_lo + (size_t)mBase * Ff;
    const __nv_bfloat16* Bh = g_WT_hi[y];
    const __nv_bfloat16* Bl = g_WT_lo[y];

    float acc[2][4][4];
#pragma unroll
    for (int mi = 0; mi < 2; mi++)
#pragma unroll
        for (int ni = 0; ni < 4; ni++)
#pragma unroll
            for (int k = 0; k < 4; k++) acc[mi][ni][k] = 0.0f;

    const int CHUNKS = 16;
    proj_issue_chunk(sb + 0 * PJ_STAGE, Ah, Al, Bh, Bl, 0, tid);
    proj_issue_chunk(sb + 1 * PJ_STAGE, Ah, Al, Bh, Bl, 1, tid);

#pragma unroll 1
    for (int c = 0; c < CHUNKS; c++) {
        if (c + 1 < CHUNKS) { CP_WAIT1(); } else { CP_WAIT0(); }
        __syncthreads();                          // stage c ready
        proj_compute_chunk(sb + (c & 1) * PJ_STAGE, tid, acc);
        __syncthreads();                          // all warps done with stage c
        if (c + 2 < CHUNKS)
            proj_issue_chunk(sb + (c & 1) * PJ_STAGE, Ah, Al, Bh, Bl, c + 2, tid);
    }

    const int lane = tid & 31, wid = tid >> 5;
    const int wm = wid & 1, wn = wid >> 1;
    const int g = lane >> 2, t2 = (lane & 3) * 2;
    __nv_bfloat16* ph = g_QK_hi[y];
    __nv_bfloat16* pl = g_QK_lo[y];
#pragma unroll
    for (int mi = 0; mi < 2; mi++)
#pragma unroll
        for (int ni = 0; ni < 4; ni++) {
            const int cc = wn * 32 + ni * 8 + t2;
#pragma unroll
            for (int half = 0; half < 2; half++) {
                const int rr = mBase + wm * 32 + mi * 16 + g + half * 8;
                float v0 = acc[mi][ni][half * 2], v1 = acc[mi][ni][half * 2 + 1];
                __nv_bfloat16 h0 = __float2bfloat16(v0), h1 = __float2bfloat16(v1);
                __nv_bfloat16 l0 = __float2bfloat16(v0 - __bfloat162float(h0));
                __nv_bfloat16 l1 = __float2bfloat16(v1 - __bfloat162float(h1));
                *(__nv_bfloat162*)(ph + (size_t)rr * De + cc) = __halves2bfloat162(h0, h1);
                *(__nv_bfloat162*)(pl + (size_t)rr * De + cc) = __halves2bfloat162(l0, l1);
            }
        }
}

// ---------------------------------------------------------------------------
// compat GEMM, persistent-j (unchanged)
#define COMPAT_SMEM (1024 + 3 * OP_BYTES)   // 197632
__global__ __launch_bounds__(GBLOCK, 1) void compat_mma_kernel(const float* __restrict__ ls_p) {
    extern __shared__ __align__(1024) char smem[];
    const int tid = threadIdx.x;
    const int jh = blockIdx.x;           // 0..1
    const int iBase = blockIdx.y * 128;  // 16 i-tiles
    const int b = blockIdx.z;
    uint32_t sb = smem_u32(smem);
    const uint32_t A  = sb + 1024;
    const uint32_t B0 = A + OP_BYTES;
    const uint32_t B1 = B0 + OP_BYTES;

    const __nv_bfloat16* Ah = g_QK_hi[0] + (size_t)(b * Nn + iBase) * De;
    const __nv_bfloat16* Al = g_QK_lo[0] + (size_t)(b * Nn + iBase) * De;
    const __nv_bfloat16* Kh = g_QK_hi[1] + (size_t)(b * Nn + jh * 1024) * De;
    const __nv_bfloat16* Kl = g_QK_lo[1] + (size_t)(b * Nn + jh * 1024) * De;

    issue_op(A,  Ah, Al, De, tid);
    issue_op(B0, Kh,            Kl,            De, tid);
    issue_op(B1, Kh + 128 * De, Kl + 128 * De, De, tid);
    CP_WAIT1();
    __syncthreads();

    const float ls = *ls_p;
    const float rsqrtD = 0.08838834764831845f;
    const int lane = tid & 31, wid = tid >> 5;
    const int wm = wid & 1, wn = wid >> 1;
    const int g = lane >> 2, t2 = (lane & 3) * 2;

#pragma unroll 1
    for (int j = 0; j < 8; j++) {
        const uint32_t Bcur = (j & 1) ? B1 : B0;

        float acc[4][4][4];
#pragma unroll
        for (int mi = 0; mi < 4; mi++)
#pragma unroll
            for (int ni = 0; ni < 4; ni++)
#pragma unroll
                for (int k = 0; k < 4; k++) acc[mi][ni][k] = 0.0f;

        compute_tile(A, Bcur, tid, acc);

        const int jBase = jh * 1024 + j * 128;
#pragma unroll
        for (int mi = 0; mi < 4; mi++)
#pragma unroll
            for (int ni = 0; ni < 4; ni++) {
                const int col = jBase + wn * 32 + ni * 8 + t2;
#pragma unroll
                for (int half = 0; half < 2; half++) {
                    const int row = iBase + wm * 64 + mi * 16 + g + half * 8;
                    float d0 = fmaxf(fabsf((float)(row - col)), 1.0f);
                    float d1 = fmaxf(fabsf((float)(row - col - 1)), 1.0f);
                    float2 v;
                    v.x = acc[mi][ni][half * 2]     * rsqrtD + __fdividef(ls, d0);
                    v.y = acc[mi][ni][half * 2 + 1] * rsqrtD + __fdividef(ls, d1);
                    *(float2*)(g_base + ((size_t)(b * Nn + row)) * Nn + col) = v;
                }
            }

        __syncthreads();
        if (j + 2 < 8) {
            issue_op(Bcur, Kh + (size_t)(j + 2) * 128 * De,
                           Kl + (size_t)(j + 2) * 128 * De, De, tid);
            CP_WAIT1();
            __syncthreads();
        } else if (j + 1 < 8) {
            CP_WAIT0();
            __syncthreads();
        }
    }
}

// ---------------------------------------------------------------------------
// Softmax pass, templated on S = number of nonzero charge components.
// logits = base * (1 + ss * dot_S(c_i, c_j)); pass 0 has constant multiplier.
// cp.async 3-stage smem pipeline; one barrier per group.
// Grid (74, 4) = 296 CTAs (2/SM, one wave). Each CTA: 27-28 rows.
#define SMX_STG   32768
#define SMX_SCI   (3 * SMX_STG)             // 98304: 32 x float4 ci
#define SMX_SRED  (SMX_SCI + 512)           // 98816: 2x4x8 floats
#define SMAX_SMEM (SMX_SRED + 256)          // 99072

__device__ __forceinline__ void smx_issue_group(
    char* smem, int stage, int b, int i0, int tid)
{
    uint32_t dst = smem_u32(smem) + stage * SMX_STG + tid * 32;
#pragma unroll
    for (int rr = 0; rr < 4; rr++) {
        const float* src = g_base + ((size_t)(b * Nn + i0 + rr)) * Nn + tid * 8;
        CP_ASYNC16(dst + rr * 8192, src);
        CP_ASYNC16(dst + rr * 8192 + 16, src + 4);
    }
    CP_COMMIT();
}

template<int S, bool WRITE_OUT>
__global__ __launch_bounds__(256, 2) void softmax_pass_kernel(
    int s, float* __restrict__ out, const float* __restrict__ ss_p)
{
    extern __shared__ __align__(16) char smem[];
    float4* s_ci = (float4*)(smem + SMX_SCI);
    float (*s_red)[4][8] = (float (*)[4][8])(smem + SMX_SRED);

    const int b = blockIdx.y;
    const int tid = threadIdx.x, lane = tid & 31, wid = tid >> 5;
    const float L2E = 1.4426950408889634f;
    const float ssl = (*ss_p) * L2E;
    const int j0 = tid * 8;

    const int rowStart = (blockIdx.x * Nn) / SM_GX;
    const int rowEnd   = ((blockIdx.x + 1) * Nn) / SM_GX;
    const int nR = rowEnd - rowStart;
    const int nG = nR >> 2;          // full 4-row groups (6 or 7)
    const int nT = nR & 3;

    // per-row charges into smem (once)
    if (S > 0 && tid < nR) s_ci[tid] = g_cpack[b * Nn + rowStart + tid];

    // column charges: only the S live components
    float cjv[(S > 0) ? S : 1][8];
    if (S > 0) {
        const float* cp = (const float*)g_cpack;
#pragma unroll
        for (int t = 0; t < 8; t++)
#pragma unroll
            for (int q = 0; q < S; q++)
                cjv[q][t] = cp[(size_t)(b * Nn + j0 + t) * 4 + q];
    }

    float col[8];
#pragma unroll
    for (int t = 0; t < 8; t++) col[t] = 0.0f;

    // pipeline prologue: up to 3 stages in flight
    for (int k = 0; k < 3 && k < nG; k++)
        smx_issue_group(smem, k, b, rowStart + 4 * k, tid);

    __syncthreads();                 // s_ci visible to all threads

#pragma unroll 1
    for (int g = 0; g < nG; g++) {
        const int rem = nG - 1 - g;
        if (rem >= 2) { CP_WAIT2(); } else if (rem == 1) { CP_WAIT1(); } else { CP_WAIT0(); }
        // no barrier: each thread reads only its own cp.async data

        const char* stg = smem + (g % 3) * SMX_STG;
        const int i0 = rowStart + g * 4;

        float lv[4][8];
        float lsum[4];
#pragma unroll
        for (int rr = 0; rr < 4; rr++) {
            float4 a0 = *(const float4*)(stg + rr * 8192 + tid * 32);
            float4 a1 = *(const float4*)(stg + rr * 8192 + tid * 32 + 16);
            float bbv[8] = {a0.x, a0.y, a0.z, a0.w, a1.x, a1.y, a1.z, a1.w};
            float cs[(S > 0) ? S : 1];
            if (S > 0) {
                float4 ci = s_ci[g * 4 + rr];
                const float* cip = (const float*)&ci;
#pragma unroll
                for (int q = 0; q < S; q++) cs[q] = cip[q] * ssl;
            }
            float acc = 0.0f;
#pragma unroll
            for (int t = 0; t < 8; t++) {
                float m = L2E;
#pragma unroll
                for (int q = 0; q < S; q++) m = fmaf(cs[q], cjv[q][t], m);
                float e = ex2f(bbv[t] * m);
                lv[rr][t] = e;
                acc += e;
            }
            lsum[rr] = acc;
        }
#pragma unroll
        for (int o = 16; o > 0; o >>= 1) {
#pragma unroll
            for (int rr = 0; rr < 4; rr++)
                lsum[rr] += __shfl_xor_sync(0xFFFFFFFFu, lsum[rr], o);
        }
        if (lane == 0) {
#pragma unroll
            for (int rr = 0; rr < 4; rr++) s_red[g & 1][rr][wid] = lsum[rr];
        }
        __syncthreads();                         // s_red visible; orders stage reuse

#pragma unroll
        for (int rr = 0; rr < 4; rr++) {
            float tot = s_red[g & 1][rr][0];
#pragma unroll
            for (int w = 1; w < 8; w++) tot += s_red[g & 1][rr][w];
            float inv = __fdividef(1.0f, tot);
            if (WRITE_OUT) {
                float4* orow = (float4*)(out + ((size_t)(b * Nn + i0 + rr)) * Nn + j0);
                orow[0] = make_float4(lv[rr][0] * inv, lv[rr][1] * inv, lv[rr][2] * inv, lv[rr][3] * inv);
                orow[1] = make_float4(lv[rr][4] * inv, lv[rr][5] * inv, lv[rr][6] * inv, lv[rr][7] * inv);
            } else {
#pragma unroll
                for (int t = 0; t < 8; t++) col[t] = fmaf(lv[rr][t], inv, col[t]);
            }
        }

        if (g + 3 < nG)
            smx_issue_group(smem, g % 3, b, rowStart + 4 * (g + 3), tid);
    }

    // tail rows (0..3), direct global loads
#pragma unroll 1
    for (int k = 0; k < nT; k++) {
        const int i0 = rowStart + nG * 4 + k;
        const float4* p = (const float4*)(g_base + ((size_t)(b * Nn + i0)) * Nn + j0);
        float4 v0 = p[0], v1 = p[1];
        float tb[8] = {v0.x, v0.y, v0.z, v0.w, v1.x, v1.y, v1.z, v1.w};

        float cs[(S > 0) ? S : 1];
        if (S > 0) {
            float4 ci = s_ci[nG * 4 + k];
            const float* cip = (const float*)&ci;
#pragma unroll
            for (int q = 0; q < S; q++) cs[q] = cip[q] * ssl;
        }
        float lsum = 0.0f;
#pragma unroll
        for (int t = 0; t < 8; t++) {
            float m = L2E;
#pragma unroll
            for (int q = 0; q < S; q++) m = fmaf(cs[q], cjv[q][t], m);
            float e = ex2f(tb[t] * m);
            tb[t] = e;
            lsum += e;
        }
#pragma unroll
        for (int o = 16; o > 0; o >>= 1) lsum += __shfl_xor_sync(0xFFFFFFFFu, lsum, o);
        if (lane == 0) s_red[k & 1][0][wid] = lsum;
        __syncthreads();
        float tot = s_red[k & 1][0][0];
#pragma unroll
        for (int w = 1; w < 8; w++) tot += s_red[k & 1][0][w];
        float inv = __fdividef(1.0f, tot);
        if (WRITE_OUT) {
            float4* orow = (float4*)(out + ((size_t)(b * Nn + i0)) * Nn + j0);
            orow[0] = make_float4(tb[0] * inv, tb[1] * inv, tb[2] * inv, tb[3] * inv);
            orow[1] = make_float4(tb[4] * inv, tb[5] * inv, tb[6] * inv, tb[7] * inv);
        } else {
#pragma unroll
            for (int t = 0; t < 8; t++) col[t] = fmaf(tb[t], inv, col[t]);
        }
        __syncthreads();
    }

    if (!WRITE_OUT) {
        float* recv = g_received + (size_t)s * NROWS + b * Nn + j0;
#pragma unroll
        for (int t = 0; t < 8; t++) atomicAdd(&recv[t], col[t]);
    }
}

// ---------------------------------------------------------------------------
// charge update: c^{s+1} = c^s * (1 - decay * sigmoid(received_s - 1))
__global__ void charge_update_kernel(int s, const float* __restrict__ decay_p) {
    int r = blockIdx.x * blockDim.x + threadIdx.x;
    if (r >= NROWS) return;
    float recv = g_received[(size_t)s * NROWS + r];
    float prev = (s == 0) ? g_c0[r] : ((float*)&g_cpack[r])[s - 1];
    float sig = 1.0f / (1.0f + __expf(-(recv - 1.0f)));
    ((float*)&g_cpack[r])[s] = prev * (1.0f - (*decay_p) * sig);
}

// ---------------------------------------------------------------------------
extern "C" void kernel_launch(void* const* d_in, const int* in_sizes, int n_in,
                              void* d_out, int out_size)
{
    const float* features = (const float*)d_in[0];
    const float* W_q      = (const float*)d_in[1];
    const float* W_k      = (const float*)d_in[2];
    const float* charge_w = (const float*)d_in[3];
    const float* charge_b = (const float*)d_in[4];
    const float* ls_p     = (const float*)d_in[5];
    const float* ss_p     = (const float*)d_in[6];
    const float* decay_p  = (const float*)d_in[7];
    float* out = (float*)d_out;

    static bool attr_set = false;
    if (!attr_set) {
        cudaFuncSetAttribute(proj_mma_kernel,   cudaFuncAttributeMaxDynamicSharedMemorySize, PROJ_SMEM);
        cudaFuncSetAttribute(compat_mma_kernel, cudaFuncAttributeMaxDynamicSharedMemorySize, COMPAT_SMEM);
        cudaFuncSetAttribute(softmax_pass_kernel<0, false>, cudaFuncAttributeMaxDynamicSharedMemorySize, SMAX_SMEM);
        cudaFuncSetAttribute(softmax_pass_kernel<1, false>, cudaFuncAttributeMaxDynamicSharedMemorySize, SMAX_SMEM);
        cudaFuncSetAttribute(softmax_pass_kernel<2, false>, cudaFuncAttributeMaxDynamicSharedMemorySize, SMAX_SMEM);
        cudaFuncSetAttribute(softmax_pass_kernel<3, false>, cudaFuncAttributeMaxDynamicSharedMemorySize, SMAX_SMEM);
        cudaFuncSetAttribute(softmax_pass_kernel<4, true>,  cudaFuncAttributeMaxDynamicSharedMemorySize, SMAX_SMEM);
        attr_set = true;
    }

    convert_all_kernel<<<2048, 256>>>(features, W_q, W_k, charge_w, charge_b);

    proj_mma_kernel<<<dim3(NROWS / 64, 2), GBLOCK, PROJ_SMEM>>>();
    compat_mma_kernel<<<dim3(2, 16, Bb), GBLOCK, COMPAT_SMEM>>>(ls_p);

    dim3 sgrid(SM_GX, Bb);
    softmax_pass_kernel<0, false><<<sgrid, 256, SMAX_SMEM>>>(0, nullptr, ss_p);
    charge_update_kernel<<<NROWS / 256, 256>>>(0, decay_p);
    softmax_pass_kernel<1, false><<<sgrid, 256, SMAX_SMEM>>>(1, nullptr, ss_p);
    charge_update_kernel<<<NROWS / 256, 256>>>(1, decay_p);
    softmax_pass_kernel<2, false><<<sgrid, 256, SMAX_SMEM>>>(2, nullptr, ss_p);
    charge_update_kernel<<<NROWS / 256, 256>>>(2, decay_p);
    softmax_pass_kernel<3, false><<<sgrid, 256, SMAX_SMEM>>>(3, nullptr, ss_p);
    charge_update_kernel<<<NROWS / 256, 256>>>(3, decay_p);
    softmax_pass_kernel<4, true><<<sgrid, 256, SMAX_SMEM>>>(0, out, ss_p);
}